// round 13
// baseline (speedup 1.0000x reference)
#include <cuda_runtime.h>
#include <cuda_bf16.h>
#include <math.h>
#include <stdint.h>

// ---------------- problem constants ----------------
#define BSZ   2
#define LSEQ  1024
#define DIM   512
#define DI    1024
#define DS    64
#define DTR   32
#define DC    4
#define ROWS  (BSZ*LSEQ)    // 2048
#define LAMB  0.01f

typedef unsigned long long u64;

// ---------------- scratch ----------------
__device__ float  g_xz  [ROWS*2*DI];
__device__ float  g_proj[ROWS*256];
__device__ float  g_dt  [ROWS*DI];
__device__ float  g_fr  [ROWS*1024];
__device__ float  g_W1  [4*256*256];
__device__ float  g_W2  [4*256*256];
__device__ float  g_b1  [4*256];
__device__ float  g_b2  [4*256];
// bf16 activations
__device__ __nv_bfloat16 g_lnh [ROWS*DIM];
__device__ __nv_bfloat16 g_xmch[ROWS*DI];
__device__ __nv_bfloat16 g_yh  [ROWS*DI];
__device__ __nv_bfloat16 g_r1h [ROWS*1024];
// bf16 weights
__device__ __nv_bfloat16 g_wie[2048*512];
__device__ __nv_bfloat16 g_woe[512*1024];
__device__ __nv_bfloat16 g_w1e[4*256*256];
__device__ __nv_bfloat16 g_w2e[4*256*256];
__device__ __nv_bfloat16 g_xcomb[1280*1024];   // rows 0..255: padded x_proj; 256..1279: Wd@Wx[:32]

__device__ __forceinline__ float silu_f(float x){ return x / (1.f + expf(-x)); }
__device__ __forceinline__ float softplus_f(float x){ return x > 20.f ? x : log1pf(expf(x)); }
__device__ __forceinline__ float shrink_f(float x){
    return x > LAMB ? x - LAMB : (x < -LAMB ? x + LAMB : 0.f);
}

// ---------------- complex helpers ----------------
__device__ __forceinline__ float2 cadd(float2 a, float2 b){ return make_float2(a.x+b.x, a.y+b.y); }
__device__ __forceinline__ float2 csub(float2 a, float2 b){ return make_float2(a.x-b.x, a.y-b.y); }
__device__ __forceinline__ float2 cmulf(float2 a, float2 b){
    return make_float2(a.x*b.x - a.y*b.y, a.x*b.y + a.y*b.x);
}

// ---------------- mma helpers ----------------
__device__ __forceinline__ uint32_t s2u(const void* p){
    uint32_t a;
    asm("{ .reg .u64 t; cvta.to.shared.u64 t, %1; cvt.u32.u64 %0, t; }" : "=r"(a) : "l"(p));
    return a;
}
__device__ __forceinline__ void ldsm4(uint32_t* r, uint32_t addr){
    asm volatile("ldmatrix.sync.aligned.m8n8.x4.shared.b16 {%0,%1,%2,%3}, [%4];"
        : "=r"(r[0]), "=r"(r[1]), "=r"(r[2]), "=r"(r[3]) : "r"(addr));
}
__device__ __forceinline__ void mma_bf16(float* c, const uint32_t* a, const uint32_t* b){
    asm volatile("mma.sync.aligned.m16n8k16.row.col.f32.bf16.bf16.f32 "
        "{%0,%1,%2,%3}, {%4,%5,%6,%7}, {%8,%9}, {%0,%1,%2,%3};"
        : "+f"(c[0]), "+f"(c[1]), "+f"(c[2]), "+f"(c[3])
        : "r"(a[0]), "r"(a[1]), "r"(a[2]), "r"(a[3]), "r"(b[0]), "r"(b[1]));
}
__device__ __forceinline__ uint4 cvt8(float4 v0, float4 v1){
    union { uint4 u; __nv_bfloat162 h[4]; } r;
    r.h[0] = __floats2bfloat162_rn(v0.x, v0.y);
    r.h[1] = __floats2bfloat162_rn(v0.z, v0.w);
    r.h[2] = __floats2bfloat162_rn(v1.x, v1.y);
    r.h[3] = __floats2bfloat162_rn(v1.z, v1.w);
    return r.u;
}
__device__ __forceinline__ uint2 cvt4(float4 v0){
    union { uint2 u; __nv_bfloat162 h[2]; } r;
    r.h[0] = __floats2bfloat162_rn(v0.x, v0.y);
    r.h[1] = __floats2bfloat162_rn(v0.z, v0.w);
    return r.u;
}

// ---------------- tensor-core bf16 GEMM: C[M,N] = A[M,K] @ B[N,K]^T ----------------
// EPI: 0 store, 2 +=, 3 relu(+bias), 4 softshrink(+bias),
//      5 column-split: col<256 -> g_proj raw, col>=256 -> softplus(+bias) -> g_dt
template<int EPI, int MI, int NI, int ABF, int CBF>
__global__ void __launch_bounds__(256,2)
k_hgemm(int K,
        const void* __restrict__ Av, int lda, long long sAz,
        const __nv_bfloat16* __restrict__ Bw, int ldb, long long sBz,
        void* __restrict__ Cv, int ldc, long long sCz,
        const float* __restrict__ bias, long long sbz)
{
    constexpr int BM = 32*MI, BN = 32*NI;
    __shared__ __align__(16) __nv_bfloat16 As[BM][40];
    __shared__ __align__(16) __nv_bfloat16 Bs[BN][40];
    const int tid = threadIdx.x, lane = tid & 31, wid = tid >> 5;
    const int wy = wid >> 2, wx = wid & 3;
    const int m0 = blockIdx.y * BM, n0 = blockIdx.x * BN;
    const float* Af = (const float*)Av + blockIdx.z * sAz;
    const __nv_bfloat16* Ah = (const __nv_bfloat16*)Av + blockIdx.z * sAz;
    Bw += blockIdx.z * sBz;
    if (EPI == 3 || EPI == 4) bias += blockIdx.z * sbz;

    float acc[MI][NI][4] = {};
    const int arow = (MI == 4) ? (tid >> 1) : (MI == 2 ? (tid >> 2) : (tid >> 3));
    const int aq   = (MI == 4) ? ((tid & 1) * 16) : (MI == 2 ? ((tid & 3) * 8) : ((tid & 7) * 4));
    const int brow = (NI == 4) ? (tid >> 1) : (tid >> 2);
    const int bq   = (NI == 4) ? ((tid & 1) * 16) : ((tid & 3) * 8);

    const int nch = K >> 5;
    float4 pa[MI]; uint4 ha0, ha1; uint2 ua;
    uint4 pb0, pb1;

    if (ABF == 0){
        const float* ap = Af + (size_t)(m0+arow)*lda + aq;
        #pragma unroll
        for (int i = 0; i < MI; i++) pa[i] = *(const float4*)(ap + 4*i);
    } else {
        const __nv_bfloat16* ap = Ah + (size_t)(m0+arow)*lda + aq;
        if (MI == 1)      ua  = *(const uint2*)(ap);
        else if (MI == 2) ha0 = *(const uint4*)(ap);
        else { ha0 = *(const uint4*)(ap); ha1 = *(const uint4*)(ap+8); }
    }
    {
        const __nv_bfloat16* bp = Bw + (size_t)(n0+brow)*ldb + bq;
        pb0 = *(const uint4*)(bp);
        if (NI == 4) pb1 = *(const uint4*)(bp+8);
    }
    if (ABF == 0){
        if (MI == 1) *(uint2*)&As[arow][aq] = cvt4(pa[0]);
        else { *(uint4*)&As[arow][aq] = cvt8(pa[0], pa[1]);
               if (MI == 4) *(uint4*)&As[arow][aq+8] = cvt8(pa[2], pa[3]); }
    } else {
        if (MI == 1) *(uint2*)&As[arow][aq] = ua;
        else { *(uint4*)&As[arow][aq] = ha0;
               if (MI == 4) *(uint4*)&As[arow][aq+8] = ha1; }
    }
    *(uint4*)&Bs[brow][bq] = pb0;
    if (NI == 4) *(uint4*)&Bs[brow][bq+8] = pb1;
    __syncthreads();

    const uint32_t sA = s2u(&As[0][0]), sB = s2u(&Bs[0][0]);
    const int q = lane >> 3, r = lane & 7;

    for (int ch = 0; ch < nch; ch++){
        if (ch + 1 < nch){
            int k0 = (ch+1) * 32;
            if (ABF == 0){
                const float* ap = Af + (size_t)(m0+arow)*lda + k0 + aq;
                #pragma unroll
                for (int i = 0; i < MI; i++) pa[i] = *(const float4*)(ap + 4*i);
            } else {
                const __nv_bfloat16* ap = Ah + (size_t)(m0+arow)*lda + k0 + aq;
                if (MI == 1)      ua  = *(const uint2*)(ap);
                else if (MI == 2) ha0 = *(const uint4*)(ap);
                else { ha0 = *(const uint4*)(ap); ha1 = *(const uint4*)(ap+8); }
            }
            const __nv_bfloat16* bp = Bw + (size_t)(n0+brow)*ldb + k0 + bq;
            pb0 = *(const uint4*)(bp);
            if (NI == 4) pb1 = *(const uint4*)(bp+8);
        }
        #pragma unroll
        for (int ks = 0; ks < 2; ks++){
            uint32_t af[MI][4], bf2[NI/2][4];
            #pragma unroll
            for (int mi = 0; mi < MI; mi++){
                int row = wy*(MI*16) + mi*16 + r + (q & 1)*8;
                int col = ks*16 + (q >> 1)*8;
                ldsm4(af[mi], sA + (uint32_t)(row*40 + col)*2);
            }
            #pragma unroll
            for (int nb = 0; nb < NI/2; nb++){
                int nrow = wx*(8*NI) + nb*16 + r + (q >> 1)*8;
                int ncol = ks*16 + (q & 1)*8;
                ldsm4(bf2[nb], sB + (uint32_t)(nrow*40 + ncol)*2);
            }
            #pragma unroll
            for (int mi = 0; mi < MI; mi++)
                #pragma unroll
                for (int ni = 0; ni < NI; ni++)
                    mma_bf16(acc[mi][ni], af[mi], &bf2[ni>>1][(ni&1)*2]);
        }
        __syncthreads();
        if (ch + 1 < nch){
            if (ABF == 0){
                if (MI == 1) *(uint2*)&As[arow][aq] = cvt4(pa[0]);
                else { *(uint4*)&As[arow][aq] = cvt8(pa[0], pa[1]);
                       if (MI == 4) *(uint4*)&As[arow][aq+8] = cvt8(pa[2], pa[3]); }
            } else {
                if (MI == 1) *(uint2*)&As[arow][aq] = ua;
                else { *(uint4*)&As[arow][aq] = ha0;
                       if (MI == 4) *(uint4*)&As[arow][aq+8] = ha1; }
            }
            *(uint4*)&Bs[brow][bq] = pb0;
            if (NI == 4) *(uint4*)&Bs[brow][bq+8] = pb1;
            __syncthreads();
        }
    }

    float* Cf = (float*)Cv + blockIdx.z * sCz;
    __nv_bfloat16* Ch = (__nv_bfloat16*)Cv + blockIdx.z * sCz;
    #pragma unroll
    for (int mi = 0; mi < MI; mi++){
        #pragma unroll
        for (int ni = 0; ni < NI; ni++){
            int row = m0 + wy*(MI*16) + mi*16 + (lane >> 2);
            int col = n0 + wx*(8*NI) + ni*8 + (lane & 3)*2;
            #pragma unroll
            for (int h = 0; h < 2; h++){
                float2 v = make_float2(acc[mi][ni][2*h], acc[mi][ni][2*h+1]);
                int rw = row + h*8;
                if (EPI == 5){
                    if (col < 256){
                        *(float2*)&g_proj[(size_t)rw*256 + col] = v;
                    } else {
                        int dc = col - 256;
                        v.x = softplus_f(v.x + bias[dc]);
                        v.y = softplus_f(v.y + bias[dc+1]);
                        *(float2*)&g_dt[(size_t)rw*1024 + dc] = v;
                    }
                    continue;
                }
                size_t off = (size_t)rw*ldc + col;
                if (EPI == 2){
                    float2 o = *(const float2*)(Cf + off);
                    v.x += o.x; v.y += o.y;
                } else if (EPI == 3){
                    v.x = fmaxf(v.x + bias[col], 0.f);
                    v.y = fmaxf(v.y + bias[col+1], 0.f);
                } else if (EPI == 4){
                    v.x = shrink_f(v.x + bias[col]);
                    v.y = shrink_f(v.y + bias[col+1]);
                }
                if (CBF) *(__nv_bfloat162*)(Ch + off) = __floats2bfloat162_rn(v.x, v.y);
                else     *(float2*)(Cf + off) = v;
            }
        }
    }
}

// ---------------- fused weight conversion ----------------
#define WN_IE  (2048*512)
#define WN_OE  (512*1024)
#define WN_W1  (4*256*256)
#define WN_W2  (4*256*256)
#define WN_XP  (256*1024)
#define WN_TOT (WN_IE+WN_OE+WN_W1+WN_W2+WN_XP)
__global__ void k_wext_all(const float* __restrict__ in_proj_w,
                           const float* __restrict__ out_proj_w,
                           const float* __restrict__ x_proj_w){
    int idx = blockIdx.x * blockDim.x + threadIdx.x;
    if (idx >= WN_TOT) return;
    float x; __nv_bfloat16* dst; int local;
    if (idx < WN_IE){ local = idx; x = in_proj_w[local]; dst = g_wie; }
    else if (idx < WN_IE+WN_OE){ local = idx - WN_IE; x = out_proj_w[local]; dst = g_woe; }
    else if (idx < WN_IE+WN_OE+WN_W1){ local = idx - WN_IE-WN_OE; x = g_W1[local]; dst = g_w1e; }
    else if (idx < WN_IE+WN_OE+WN_W1+WN_W2){ local = idx - WN_IE-WN_OE-WN_W1; x = g_W2[local]; dst = g_w2e; }
    else {
        local = idx - WN_IE-WN_OE-WN_W1-WN_W2;
        int n = local >> 10, k = local & 1023;
        x = (n < 160) ? x_proj_w[n*1024 + k] : 0.f;
        dst = g_xcomb;
    }
    dst[local] = __float2bfloat16_rn(x);
}

// ---------------- Wcomb = Wd @ Wx[:32]  -> g_xcomb rows 256..1279 ----------------
__global__ void k_wcomb(const float* __restrict__ dtw, const float* __restrict__ xpw){
    int idx = blockIdx.x * blockDim.x + threadIdx.x;   // 1024*1024
    int d = idx >> 10, k = idx & 1023;
    float s = 0.f;
    #pragma unroll
    for (int j = 0; j < 32; j++)
        s = fmaf(dtw[d*32 + j], xpw[j*1024 + k], s);
    g_xcomb[(size_t)(256 + d)*1024 + k] = __float2bfloat16_rn(s);
}

// ---------------- layernorm -> bf16 ----------------
__global__ void k_layernorm(const float* __restrict__ x, const float* __restrict__ w,
                            const float* __restrict__ b, __nv_bfloat16* __restrict__ out){
    int row = blockIdx.x;
    const float* xr = x + (size_t)row * DIM;
    int tid = threadIdx.x;
    float v0 = xr[tid], v1 = xr[tid + 256];
    float s = v0 + v1, q = v0*v0 + v1*v1;
    __shared__ float ss[8], sq[8];
    for (int o = 16; o; o >>= 1){ s += __shfl_down_sync(~0u, s, o); q += __shfl_down_sync(~0u, q, o); }
    if ((tid & 31) == 0){ ss[tid >> 5] = s; sq[tid >> 5] = q; }
    __syncthreads();
    __shared__ float mean_s, rstd_s;
    if (tid == 0){
        float S = 0.f, Q = 0.f;
        #pragma unroll
        for (int i = 0; i < 8; i++){ S += ss[i]; Q += sq[i]; }
        float m = S * (1.f/DIM);
        float var = Q * (1.f/DIM) - m*m;
        mean_s = m; rstd_s = rsqrtf(var + 1e-5f);
    }
    __syncthreads();
    float m = mean_s, rr = rstd_s;
    out[(size_t)row*DIM + tid]       = __float2bfloat16_rn((v0 - m)*rr*w[tid]       + b[tid]);
    out[(size_t)row*DIM + tid + 256] = __float2bfloat16_rn((v1 - m)*rr*w[tid + 256] + b[tid + 256]);
}

// ---------------- fused layernorm + forward DFT-4 ----------------
__global__ void k_layernorm_fft(const float* __restrict__ x, const float* __restrict__ w,
                                const float* __restrict__ b){
    int row = blockIdx.x;
    const float* xr = x + (size_t)row * DIM;
    int tid = threadIdx.x;
    __shared__ float sx[DIM];
    float v0 = xr[tid], v1 = xr[tid + 256];
    float s = v0 + v1, q = v0*v0 + v1*v1;
    __shared__ float ss[8], sq[8];
    for (int o = 16; o; o >>= 1){ s += __shfl_down_sync(~0u, s, o); q += __shfl_down_sync(~0u, q, o); }
    if ((tid & 31) == 0){ ss[tid >> 5] = s; sq[tid >> 5] = q; }
    __syncthreads();
    __shared__ float mean_s, rstd_s;
    if (tid == 0){
        float S = 0.f, Q = 0.f;
        #pragma unroll
        for (int i = 0; i < 8; i++){ S += ss[i]; Q += sq[i]; }
        float m = S * (1.f/DIM);
        float var = Q * (1.f/DIM) - m*m;
        mean_s = m; rstd_s = rsqrtf(var + 1e-5f);
    }
    __syncthreads();
    float m = mean_s, rr = rstd_s;
    sx[tid]       = (v0 - m)*rr*w[tid]       + b[tid];
    sx[tid + 256] = (v1 - m)*rr*w[tid + 256] + b[tid + 256];
    __syncthreads();
    if (tid < 128){
        int j = tid;
        float x0 = sx[j], x1 = sx[j+128], x2 = sx[j+256], x3 = sx[j+384];
        float* qq = g_fr + (size_t)row * 1024 + j;
        qq[0]   = x0 + x1 + x2 + x3;  qq[128] = 0.f;
        qq[256] = x0 - x2;            qq[384] = -(x1 - x3);
        qq[512] = x0 - x1 + x2 - x3;  qq[640] = 0.f;
        qq[768] = x0 - x2;            qq[896] = x1 - x3;
    }
}

// ---------------- causal depthwise conv + silu -> bf16 ----------------
__global__ void k_conv_silu(const float* __restrict__ conv_w, const float* __restrict__ conv_b){
    int idx = blockIdx.x * blockDim.x + threadIdx.x;
    if (idx >= ROWS * DI) return;
    int c = idx & (DI - 1);
    int l = (idx >> 10) & (LSEQ - 1);
    int b = idx >> 20;
    const float* xm = g_xz + (size_t)b * LSEQ * (2*DI);
    float acc = conv_b[c];
    #pragma unroll
    for (int k = 0; k < DC; k++){
        int lp = l + k - (DC - 1);
        if (lp >= 0) acc = fmaf(conv_w[c*DC + k], xm[(size_t)lp*(2*DI) + c], acc);
    }
    g_xmch[idx] = __float2bfloat16_rn(silu_f(acc));
}

// ---------------- selective scan + fused gate ----------------
#define SC_LT 16
__global__ void __launch_bounds__(256) k_scan2(const float* __restrict__ A_log,
                                               const float* __restrict__ Dv){
    __shared__ float sdt[SC_LT][8], su[SC_LT][8];
    __shared__ float sB[SC_LT][64], sC[SC_LT][64];
    __shared__ float sy[SC_LT][8];
    const int tid = threadIdx.x, w = tid >> 5, lane = tid & 31;
    const int b = blockIdx.x >> 7;
    const int dblk = blockIdx.x & 127;
    const int d0 = dblk * 8;
    const int d = d0 + w;
    const float A0 = -__expf(A_log[d*DS + lane]);
    const float A1 = -__expf(A_log[d*DS + 32 + lane]);
    const float* pdt = g_dt + (size_t)b*LSEQ*DI;
    const __nv_bfloat16* puh = g_xmch + (size_t)b*LSEQ*DI;
    const float* pp  = g_proj + (size_t)b*LSEQ*256;
    const float* pz  = g_xz   + (size_t)b*LSEQ*(2*DI) + DI;
    __nv_bfloat16* py = g_yh  + (size_t)b*LSEQ*DI;
    float h0 = 0.f, h1 = 0.f;
    for (int l0 = 0; l0 < LSEQ; l0 += SC_LT){
        if (tid < SC_LT*8){
            int s = tid >> 3, j = tid & 7;
            sdt[s][j] = pdt[(size_t)(l0+s)*DI + d0 + j];
            su [s][j] = __bfloat162float(puh[(size_t)(l0+s)*DI + d0 + j]);
        }
        {
            int s = tid >> 4, j4 = tid & 15;
            const float* pr = pp + (size_t)(l0+s)*256;
            *(float4*)&sB[s][j4*4] = *(const float4*)(pr + 32 + j4*4);
            *(float4*)&sC[s][j4*4] = *(const float4*)(pr + 96 + j4*4);
        }
        __syncthreads();
        float dA0[SC_LT], dA1[SC_LT], du[SC_LT];
        #pragma unroll
        for (int s = 0; s < SC_LT; s++){
            float dtv = sdt[s][w];
            dA0[s] = __expf(dtv*A0);
            dA1[s] = __expf(dtv*A1);
            du[s]  = dtv * su[s][w];
        }
        #pragma unroll
        for (int half = 0; half < 2; half++){
            float hs0[8], hs1[8];
            #pragma unroll
            for (int t = 0; t < 8; t++){
                int s = half*8 + t;
                h0 = fmaf(dA0[s], h0, du[s]*sB[s][lane]);
                h1 = fmaf(dA1[s], h1, du[s]*sB[s][lane+32]);
                hs0[t] = h0; hs1[t] = h1;
            }
            #pragma unroll
            for (int t = 0; t < 8; t++){
                int s = half*8 + t;
                float yv = hs0[t]*sC[s][lane] + hs1[t]*sC[s][lane+32];
                #pragma unroll
                for (int o = 16; o; o >>= 1) yv += __shfl_down_sync(~0u, yv, o);
                if (lane == 0) sy[s][w] = yv;
            }
        }
        __syncthreads();
        if (tid < SC_LT*8){
            int s = tid >> 3, j = tid & 7;
            size_t off = (size_t)(l0+s)*DI + d0 + j;
            float z = pz[(size_t)(l0+s)*(2*DI) + d0 + j];
            float y = fmaf(su[s][j], Dv[d0+j], sy[s][j]);
            py[off] = __float2bfloat16_rn(y * silu_f(z));
        }
        __syncthreads();
    }
}

// ---------------- build EinFFT real-GEMM weights/biases ----------------
__global__ void k_build(const float* __restrict__ cw1, const float* __restrict__ cw2,
                        const float* __restrict__ cb1, const float* __restrict__ cb2){
    int idx = blockIdx.x * blockDim.x + threadIdx.x;
    if (idx >= 4*256*256) return;
    int k = idx & 255, n = (idx >> 8) & 255, b = idx >> 16;
    int j = n & 127, d = k & 127;
    bool nre = n < 128, kre = k < 128;
    float w0a = cw1[b*16384 + d*128 + j];
    float w1a = cw1[65536 + b*16384 + d*128 + j];
    g_W1[idx] = nre ? (kre ? w0a : -w1a) : (kre ? w1a : w0a);
    float w0b = cw2[b*16384 + d*128 + j];
    float w1b = cw2[65536 + b*16384 + d*128 + j];
    g_W2[idx] = nre ? (kre ? w0b : -w1b) : (kre ? w1b : w0b);
    if (k == 0){
        g_b1[b*256 + n] = nre ? cb1[b*128 + j] : cb1[512 + b*128 + j];
        g_b2[b*256 + n] = nre ? cb2[b*128 + j] : cb2[512 + b*128 + j];
    }
}

// ---------------- 1024-pt radix-4 FFT along N, 4 columns/block (256 CTAs) ----------------
__global__ void k_fft1024r4(float sign){
    extern __shared__ float2 shm[];
    float2* tw = shm;
    float2* sh = shm + 1024;
    const int tid = threadIdx.x; // 512
    int blk = blockIdx.x;
    int b = blk >> 7;
    int rem = blk & 127;
    int kblk = rem >> 5, j4 = rem & 31;
    float* base = g_fr + (size_t)b * 1024 * 1024 + kblk*256 + j4*4;

    #pragma unroll
    for (int r = 0; r < 2; r++){
        int i = tid + r*512;
        float s, cc;
        sincosf(sign * 6.283185307179586f * (float)i / 1024.f, &s, &cc);
        tw[i] = make_float2(cc, s);
    }

    #pragma unroll
    for (int r = 0; r < 2; r++){
        int n = tid + r*512;
        int rv = ((n & 3) << 8) | (((n >> 2) & 3) << 6) | (((n >> 4) & 3) << 4)
               | (((n >> 6) & 3) << 2) | ((n >> 8) & 3);
        float4 re = *(const float4*)(base + (size_t)n*1024);
        float4 im = *(const float4*)(base + (size_t)n*1024 + 128);
        sh[0*1025 + rv] = make_float2(re.x, im.x);
        sh[1*1025 + rv] = make_float2(re.y, im.y);
        sh[2*1025 + rv] = make_float2(re.z, im.z);
        sh[3*1025 + rv] = make_float2(re.w, im.w);
    }
    __syncthreads();

    const int c = tid & 3, bf0 = tid >> 2;
    float2* S = sh + c*1025;
    #pragma unroll
    for (int st = 0; st < 5; st++){
        const int q = 1 << (2*st);
        const int tsh = 8 - 2*st;
        #pragma unroll
        for (int r = 0; r < 2; r++){
            int bf = bf0 + r*128;
            int j = bf & (q - 1);
            int i1 = ((bf & ~(q - 1)) << 2) | j;
            float2 x0 = S[i1], x1 = S[i1+q], x2 = S[i1+2*q], x3 = S[i1+3*q];
            if (st > 0){
                int j1 = j << tsh;
                x1 = cmulf(x1, tw[j1]);
                x2 = cmulf(x2, tw[2*j1]);
                x3 = cmulf(x3, tw[3*j1]);
            }
            float2 t0 = cadd(x0, x2), t1 = csub(x0, x2);
            float2 t2 = cadd(x1, x3), t3 = csub(x1, x3);
            float2 t3r = make_float2(-sign*t3.y, sign*t3.x);
            S[i1]       = cadd(t0, t2);
            S[i1+q]     = cadd(t1, t3r);
            S[i1+2*q]   = csub(t0, t2);
            S[i1+3*q]   = csub(t1, t3r);
        }
        __syncthreads();
    }

    const float sc = 0.015625f;
    #pragma unroll
    for (int r = 0; r < 2; r++){
        int n = tid + r*512;
        float2 v0 = sh[0*1025 + n], v1 = sh[1*1025 + n];
        float2 v2 = sh[2*1025 + n], v3 = sh[3*1025 + n];
        *(float4*)(base + (size_t)n*1024)       = make_float4(v0.x*sc, v1.x*sc, v2.x*sc, v3.x*sc);
        *(float4*)(base + (size_t)n*1024 + 128) = make_float4(v0.y*sc, v1.y*sc, v2.y*sc, v3.y*sc);
    }
}
#define FFT_SMEM ((1024 + 4*1025) * 8)

// ---------------- inverse 4-point DFT along NB, real part, add into out ----------------
__global__ void k_fft4_inv_add(float* __restrict__ out){
    int idx = blockIdx.x * blockDim.x + threadIdx.x;
    if (idx >= ROWS * 128) return;
    int j = idx & 127, row = idx >> 7;
    const float* q = g_fr + (size_t)row * 1024 + j;
    float r0 = q[0];
    float r1 = q[256], i1 = q[384];
    float r2 = q[512];
    float r3 = q[768], i3 = q[896];
    float* o = out + (size_t)row * DIM + j;
    o[0]   += r0 + r1 + r2 + r3;
    o[128] += r0 - i1 - r2 + i3;
    o[256] += r0 - r1 + r2 - r3;
    o[384] += r0 + i1 - r2 - i3;
}

// ---------------- host launch ----------------
extern "C" void kernel_launch(void* const* d_in, const int* in_sizes, int n_in,
                              void* d_out, int out_size){
    const float* x_in      = (const float*)d_in[0];
    const float* ln_w      = (const float*)d_in[1];
    const float* ln_b      = (const float*)d_in[2];
    const float* in_proj_w = (const float*)d_in[3];
    const float* conv_w    = (const float*)d_in[4];
    const float* conv_b    = (const float*)d_in[5];
    const float* x_proj_w  = (const float*)d_in[6];
    const float* dt_proj_w = (const float*)d_in[7];
    const float* dt_proj_b = (const float*)d_in[8];
    const float* A_log     = (const float*)d_in[9];
    const float* Dv        = (const float*)d_in[10];
    const float* out_proj_w= (const float*)d_in[11];
    const float* norm2_w   = (const float*)d_in[12];
    const float* norm2_b   = (const float*)d_in[13];
    const float* cw1       = (const float*)d_in[14];
    const float* cw2       = (const float*)d_in[15];
    const float* cb1       = (const float*)d_in[16];
    const float* cb2       = (const float*)d_in[17];
    float* xout = (float*)d_out;

    float *p_xz, *p_fr, *p_b1, *p_b2;
    __nv_bfloat16 *p_lnh, *p_xmch, *p_yh, *p_r1h, *p_wie, *p_woe, *p_w1e, *p_w2e, *p_xcomb;
    cudaGetSymbolAddress((void**)&p_xz,    g_xz);
    cudaGetSymbolAddress((void**)&p_fr,    g_fr);
    cudaGetSymbolAddress((void**)&p_b1,    g_b1);
    cudaGetSymbolAddress((void**)&p_b2,    g_b2);
    cudaGetSymbolAddress((void**)&p_lnh,   g_lnh);
    cudaGetSymbolAddress((void**)&p_xmch,  g_xmch);
    cudaGetSymbolAddress((void**)&p_yh,    g_yh);
    cudaGetSymbolAddress((void**)&p_r1h,   g_r1h);
    cudaGetSymbolAddress((void**)&p_wie,   g_wie);
    cudaGetSymbolAddress((void**)&p_woe,   g_woe);
    cudaGetSymbolAddress((void**)&p_w1e,   g_w1e);
    cudaGetSymbolAddress((void**)&p_w2e,   g_w2e);
    cudaGetSymbolAddress((void**)&p_xcomb, g_xcomb);

    float *p_proj, *p_dtg;
    cudaGetSymbolAddress((void**)&p_proj, g_proj);
    cudaGetSymbolAddress((void**)&p_dtg,  g_dt);
    (void)p_proj; (void)p_dtg;

    cudaFuncSetAttribute(k_fft1024r4, cudaFuncAttributeMaxDynamicSharedMemorySize, FFT_SMEM);

    cudaMemcpyAsync(xout, x_in, (size_t)ROWS*DIM*sizeof(float), cudaMemcpyDeviceToDevice, 0);

    k_build<<<(4*256*256 + 255)/256, 256>>>(cw1, cw2, cb1, cb2);
    k_wext_all<<<(WN_TOT + 255)/256, 256>>>(in_proj_w, out_proj_w, x_proj_w);
    k_wcomb<<<(1024*1024 + 255)/256, 256>>>(dt_proj_w, x_proj_w);

    for (int blk = 0; blk < 2; blk++){
        // ---- Mamba ----
        k_layernorm<<<ROWS, 256>>>(xout, ln_w, ln_b, p_lnh);
        k_hgemm<0,4,4,1,0><<<dim3(16,16,1), 256>>>(512,
            p_lnh, DIM, 0, p_wie, 512, 0, p_xz, 2*DI, 0, nullptr, 0);
        k_conv_silu<<<(ROWS*DI + 255)/256, 256>>>(conv_w, conv_b);
        // combined x_proj + dt_proj (column-split epilogue)
        k_hgemm<5,2,4,1,0><<<dim3(10,32,1), 256>>>(1024,
            p_xmch, DI, 0, p_xcomb, 1024, 0, nullptr, 0, 0, dt_proj_b, 0);
        k_scan2<<<256, 256>>>(A_log, Dv);
        k_hgemm<2,2,2,1,0><<<dim3(8,32,1), 256>>>(1024,
            p_yh, DI, 0, p_woe, 1024, 0, xout, DIM, 0, nullptr, 0);

        // ---- EinFFT ----
        k_layernorm_fft<<<ROWS, 256>>>(xout, norm2_w, norm2_b);
        k_fft1024r4<<<256, 512, FFT_SMEM>>>(-1.f);
        k_hgemm<3,2,2,0,1><<<dim3(4,32,4), 256>>>(256,
            p_fr, 1024, 256, p_w1e, 256, 256*256, p_r1h, 1024, 256, p_b1, 256);
        k_hgemm<4,2,2,1,0><<<dim3(4,32,4), 256>>>(256,
            p_r1h, 1024, 256, p_w2e, 256, 256*256, p_fr, 1024, 256, p_b2, 256);
        k_fft1024r4<<<256, 512, FFT_SMEM>>>(1.f);
        k_fft4_inv_add<<<(ROWS*128 + 255)/256, 256>>>(xout);
    }
}

// round 14
// speedup vs baseline: 1.1072x; 1.1072x over previous
#include <cuda_runtime.h>
#include <cuda_bf16.h>
#include <math.h>
#include <stdint.h>

// ---------------- problem constants ----------------
#define BSZ   2
#define LSEQ  1024
#define DIM   512
#define DI    1024
#define DS    64
#define DTR   32
#define DC    4
#define ROWS  (BSZ*LSEQ)    // 2048
#define LAMB  0.01f

typedef unsigned long long u64;

// ---------------- scratch ----------------
__device__ float  g_xz  [ROWS*2*DI];
__device__ float  g_proj[ROWS*256];
__device__ float  g_dt  [ROWS*DI];
__device__ float  g_fr  [ROWS*1024];
__device__ float  g_W1  [4*256*256];
__device__ float  g_W2  [4*256*256];
__device__ float  g_b1  [4*256];
__device__ float  g_b2  [4*256];
// bf16 activations
__device__ __nv_bfloat16 g_lnh [ROWS*DIM];
__device__ __nv_bfloat16 g_xmch[ROWS*DI];
__device__ __nv_bfloat16 g_yh  [ROWS*DI];
__device__ __nv_bfloat16 g_r1h [ROWS*1024];
// bf16 weights
__device__ __nv_bfloat16 g_wie[2048*512];
__device__ __nv_bfloat16 g_woe[512*1024];
__device__ __nv_bfloat16 g_wde[1024*32];
__device__ __nv_bfloat16 g_w1e[4*256*256];
__device__ __nv_bfloat16 g_w2e[4*256*256];
__device__ __nv_bfloat16 g_xpe[256*1024];

__device__ __forceinline__ float silu_f(float x){ return x / (1.f + expf(-x)); }
__device__ __forceinline__ float softplus_f(float x){ return x > 20.f ? x : log1pf(expf(x)); }
__device__ __forceinline__ float shrink_f(float x){
    return x > LAMB ? x - LAMB : (x < -LAMB ? x + LAMB : 0.f);
}

// ---------------- complex helpers ----------------
__device__ __forceinline__ float2 cadd(float2 a, float2 b){ return make_float2(a.x+b.x, a.y+b.y); }
__device__ __forceinline__ float2 csub(float2 a, float2 b){ return make_float2(a.x-b.x, a.y-b.y); }
__device__ __forceinline__ float2 cmulf(float2 a, float2 b){
    return make_float2(a.x*b.x - a.y*b.y, a.x*b.y + a.y*b.x);
}

// ---------------- mma helpers ----------------
__device__ __forceinline__ uint32_t s2u(const void* p){
    uint32_t a;
    asm("{ .reg .u64 t; cvta.to.shared.u64 t, %1; cvt.u32.u64 %0, t; }" : "=r"(a) : "l"(p));
    return a;
}
__device__ __forceinline__ void ldsm4(uint32_t* r, uint32_t addr){
    asm volatile("ldmatrix.sync.aligned.m8n8.x4.shared.b16 {%0,%1,%2,%3}, [%4];"
        : "=r"(r[0]), "=r"(r[1]), "=r"(r[2]), "=r"(r[3]) : "r"(addr));
}
__device__ __forceinline__ void mma_bf16(float* c, const uint32_t* a, const uint32_t* b){
    asm volatile("mma.sync.aligned.m16n8k16.row.col.f32.bf16.bf16.f32 "
        "{%0,%1,%2,%3}, {%4,%5,%6,%7}, {%8,%9}, {%0,%1,%2,%3};"
        : "+f"(c[0]), "+f"(c[1]), "+f"(c[2]), "+f"(c[3])
        : "r"(a[0]), "r"(a[1]), "r"(a[2]), "r"(a[3]), "r"(b[0]), "r"(b[1]));
}
__device__ __forceinline__ uint4 cvt8(float4 v0, float4 v1){
    union { uint4 u; __nv_bfloat162 h[4]; } r;
    r.h[0] = __floats2bfloat162_rn(v0.x, v0.y);
    r.h[1] = __floats2bfloat162_rn(v0.z, v0.w);
    r.h[2] = __floats2bfloat162_rn(v1.x, v1.y);
    r.h[3] = __floats2bfloat162_rn(v1.z, v1.w);
    return r.u;
}
__device__ __forceinline__ uint2 cvt4(float4 v0){
    union { uint2 u; __nv_bfloat162 h[2]; } r;
    r.h[0] = __floats2bfloat162_rn(v0.x, v0.y);
    r.h[1] = __floats2bfloat162_rn(v0.z, v0.w);
    return r.u;
}

// ---------------- tensor-core bf16 GEMM: C[M,N] = A[M,K] @ B[N,K]^T ----------------
// BM=32*MI (MI in {1,2,4}), BN=32*NI (NI in {2,4}), chunk = 32 K, 256 thr (8 warps 2x4).
// ABF: A stored bf16; CBF: store C as bf16.
// EPI: 0 store, 1 softplus(+bias), 2 +=, 3 relu(+bias), 4 softshrink(+bias)
template<int EPI, int MI, int NI, int ABF, int CBF>
__global__ void __launch_bounds__(256,2)
k_hgemm(int K,
        const void* __restrict__ Av, int lda, long long sAz,
        const __nv_bfloat16* __restrict__ Bw, int ldb, long long sBz,
        void* __restrict__ Cv, int ldc, long long sCz,
        const float* __restrict__ bias, long long sbz)
{
    constexpr int BM = 32*MI, BN = 32*NI;
    __shared__ __align__(16) __nv_bfloat16 As[BM][40];
    __shared__ __align__(16) __nv_bfloat16 Bs[BN][40];
    const int tid = threadIdx.x, lane = tid & 31, wid = tid >> 5;
    const int wy = wid >> 2, wx = wid & 3;
    const int m0 = blockIdx.y * BM, n0 = blockIdx.x * BN;
    const float* Af = (const float*)Av + blockIdx.z * sAz;
    const __nv_bfloat16* Ah = (const __nv_bfloat16*)Av + blockIdx.z * sAz;
    Bw += blockIdx.z * sBz;
    if (EPI == 1 || EPI == 3 || EPI == 4) bias += blockIdx.z * sbz;

    float acc[MI][NI][4] = {};
    const int arow = (MI == 4) ? (tid >> 1) : (MI == 2 ? (tid >> 2) : (tid >> 3));
    const int aq   = (MI == 4) ? ((tid & 1) * 16) : (MI == 2 ? ((tid & 3) * 8) : ((tid & 7) * 4));
    const int brow = (NI == 4) ? (tid >> 1) : (tid >> 2);
    const int bq   = (NI == 4) ? ((tid & 1) * 16) : ((tid & 3) * 8);

    const int nch = K >> 5;
    float4 pa[MI]; uint4 ha0, ha1; uint2 ua;
    uint4 pb0, pb1;

    if (ABF == 0){
        const float* ap = Af + (size_t)(m0+arow)*lda + aq;
        #pragma unroll
        for (int i = 0; i < MI; i++) pa[i] = *(const float4*)(ap + 4*i);
    } else {
        const __nv_bfloat16* ap = Ah + (size_t)(m0+arow)*lda + aq;
        if (MI == 1)      ua  = *(const uint2*)(ap);
        else if (MI == 2) ha0 = *(const uint4*)(ap);
        else { ha0 = *(const uint4*)(ap); ha1 = *(const uint4*)(ap+8); }
    }
    {
        const __nv_bfloat16* bp = Bw + (size_t)(n0+brow)*ldb + bq;
        pb0 = *(const uint4*)(bp);
        if (NI == 4) pb1 = *(const uint4*)(bp+8);
    }
    if (ABF == 0){
        if (MI == 1) *(uint2*)&As[arow][aq] = cvt4(pa[0]);
        else { *(uint4*)&As[arow][aq] = cvt8(pa[0], pa[1]);
               if (MI == 4) *(uint4*)&As[arow][aq+8] = cvt8(pa[2], pa[3]); }
    } else {
        if (MI == 1) *(uint2*)&As[arow][aq] = ua;
        else { *(uint4*)&As[arow][aq] = ha0;
               if (MI == 4) *(uint4*)&As[arow][aq+8] = ha1; }
    }
    *(uint4*)&Bs[brow][bq] = pb0;
    if (NI == 4) *(uint4*)&Bs[brow][bq+8] = pb1;
    __syncthreads();

    const uint32_t sA = s2u(&As[0][0]), sB = s2u(&Bs[0][0]);
    const int q = lane >> 3, r = lane & 7;

    for (int ch = 0; ch < nch; ch++){
        if (ch + 1 < nch){
            int k0 = (ch+1) * 32;
            if (ABF == 0){
                const float* ap = Af + (size_t)(m0+arow)*lda + k0 + aq;
                #pragma unroll
                for (int i = 0; i < MI; i++) pa[i] = *(const float4*)(ap + 4*i);
            } else {
                const __nv_bfloat16* ap = Ah + (size_t)(m0+arow)*lda + k0 + aq;
                if (MI == 1)      ua  = *(const uint2*)(ap);
                else if (MI == 2) ha0 = *(const uint4*)(ap);
                else { ha0 = *(const uint4*)(ap); ha1 = *(const uint4*)(ap+8); }
            }
            const __nv_bfloat16* bp = Bw + (size_t)(n0+brow)*ldb + k0 + bq;
            pb0 = *(const uint4*)(bp);
            if (NI == 4) pb1 = *(const uint4*)(bp+8);
        }
        #pragma unroll
        for (int ks = 0; ks < 2; ks++){
            uint32_t af[MI][4], bf2[NI/2][4];
            #pragma unroll
            for (int mi = 0; mi < MI; mi++){
                int row = wy*(MI*16) + mi*16 + r + (q & 1)*8;
                int col = ks*16 + (q >> 1)*8;
                ldsm4(af[mi], sA + (uint32_t)(row*40 + col)*2);
            }
            #pragma unroll
            for (int nb = 0; nb < NI/2; nb++){
                int nrow = wx*(8*NI) + nb*16 + r + (q >> 1)*8;
                int ncol = ks*16 + (q & 1)*8;
                ldsm4(bf2[nb], sB + (uint32_t)(nrow*40 + ncol)*2);
            }
            #pragma unroll
            for (int mi = 0; mi < MI; mi++)
                #pragma unroll
                for (int ni = 0; ni < NI; ni++)
                    mma_bf16(acc[mi][ni], af[mi], &bf2[ni>>1][(ni&1)*2]);
        }
        __syncthreads();
        if (ch + 1 < nch){
            if (ABF == 0){
                if (MI == 1) *(uint2*)&As[arow][aq] = cvt4(pa[0]);
                else { *(uint4*)&As[arow][aq] = cvt8(pa[0], pa[1]);
                       if (MI == 4) *(uint4*)&As[arow][aq+8] = cvt8(pa[2], pa[3]); }
            } else {
                if (MI == 1) *(uint2*)&As[arow][aq] = ua;
                else { *(uint4*)&As[arow][aq] = ha0;
                       if (MI == 4) *(uint4*)&As[arow][aq+8] = ha1; }
            }
            *(uint4*)&Bs[brow][bq] = pb0;
            if (NI == 4) *(uint4*)&Bs[brow][bq+8] = pb1;
            __syncthreads();
        }
    }

    float* Cf = (float*)Cv + blockIdx.z * sCz;
    __nv_bfloat16* Ch = (__nv_bfloat16*)Cv + blockIdx.z * sCz;
    #pragma unroll
    for (int mi = 0; mi < MI; mi++){
        #pragma unroll
        for (int ni = 0; ni < NI; ni++){
            int row = m0 + wy*(MI*16) + mi*16 + (lane >> 2);
            int col = n0 + wx*(8*NI) + ni*8 + (lane & 3)*2;
            #pragma unroll
            for (int h = 0; h < 2; h++){
                float2 v = make_float2(acc[mi][ni][2*h], acc[mi][ni][2*h+1]);
                size_t off = (size_t)(row + h*8)*ldc + col;
                if (EPI == 1){
                    v.x = softplus_f(v.x + bias[col]);
                    v.y = softplus_f(v.y + bias[col+1]);
                } else if (EPI == 2){
                    float2 o = *(const float2*)(Cf + off);
                    v.x += o.x; v.y += o.y;
                } else if (EPI == 3){
                    v.x = fmaxf(v.x + bias[col], 0.f);
                    v.y = fmaxf(v.y + bias[col+1], 0.f);
                } else if (EPI == 4){
                    v.x = shrink_f(v.x + bias[col]);
                    v.y = shrink_f(v.y + bias[col+1]);
                }
                if (CBF) *(__nv_bfloat162*)(Ch + off) = __floats2bfloat162_rn(v.x, v.y);
                else     *(float2*)(Cf + off) = v;
            }
        }
    }
}

// ---------------- fused weight conversion ----------------
#define WN_IE  (2048*512)
#define WN_OE  (512*1024)
#define WN_DE  (1024*32)
#define WN_W1  (4*256*256)
#define WN_W2  (4*256*256)
#define WN_XP  (256*1024)
#define WN_TOT (WN_IE+WN_OE+WN_DE+WN_W1+WN_W2+WN_XP)
__global__ void k_wext_all(const float* __restrict__ in_proj_w,
                           const float* __restrict__ out_proj_w,
                           const float* __restrict__ dt_proj_w,
                           const float* __restrict__ x_proj_w){
    int idx = blockIdx.x * blockDim.x + threadIdx.x;
    if (idx >= WN_TOT) return;
    float x; __nv_bfloat16* dst; int local;
    if (idx < WN_IE){ local = idx; x = in_proj_w[local]; dst = g_wie; }
    else if (idx < WN_IE+WN_OE){ local = idx - WN_IE; x = out_proj_w[local]; dst = g_woe; }
    else if (idx < WN_IE+WN_OE+WN_DE){ local = idx - WN_IE-WN_OE; x = dt_proj_w[local]; dst = g_wde; }
    else if (idx < WN_IE+WN_OE+WN_DE+WN_W1){ local = idx - WN_IE-WN_OE-WN_DE; x = g_W1[local]; dst = g_w1e; }
    else if (idx < WN_IE+WN_OE+WN_DE+WN_W1+WN_W2){ local = idx - WN_IE-WN_OE-WN_DE-WN_W1; x = g_W2[local]; dst = g_w2e; }
    else {
        local = idx - WN_IE-WN_OE-WN_DE-WN_W1-WN_W2;
        int n = local >> 10, k = local & 1023;
        x = (n < 160) ? x_proj_w[n*1024 + k] : 0.f;
        dst = g_xpe;
    }
    dst[local] = __float2bfloat16_rn(x);
}

// ---------------- layernorm -> bf16 ----------------
__global__ void k_layernorm(const float* __restrict__ x, const float* __restrict__ w,
                            const float* __restrict__ b, __nv_bfloat16* __restrict__ out){
    int row = blockIdx.x;
    const float* xr = x + (size_t)row * DIM;
    int tid = threadIdx.x;
    float v0 = xr[tid], v1 = xr[tid + 256];
    float s = v0 + v1, q = v0*v0 + v1*v1;
    __shared__ float ss[8], sq[8];
    for (int o = 16; o; o >>= 1){ s += __shfl_down_sync(~0u, s, o); q += __shfl_down_sync(~0u, q, o); }
    if ((tid & 31) == 0){ ss[tid >> 5] = s; sq[tid >> 5] = q; }
    __syncthreads();
    __shared__ float mean_s, rstd_s;
    if (tid == 0){
        float S = 0.f, Q = 0.f;
        #pragma unroll
        for (int i = 0; i < 8; i++){ S += ss[i]; Q += sq[i]; }
        float m = S * (1.f/DIM);
        float var = Q * (1.f/DIM) - m*m;
        mean_s = m; rstd_s = rsqrtf(var + 1e-5f);
    }
    __syncthreads();
    float m = mean_s, rr = rstd_s;
    out[(size_t)row*DIM + tid]       = __float2bfloat16_rn((v0 - m)*rr*w[tid]       + b[tid]);
    out[(size_t)row*DIM + tid + 256] = __float2bfloat16_rn((v1 - m)*rr*w[tid + 256] + b[tid + 256]);
}

// ---------------- fused layernorm + forward DFT-4 ----------------
__global__ void k_layernorm_fft(const float* __restrict__ x, const float* __restrict__ w,
                                const float* __restrict__ b){
    int row = blockIdx.x;
    const float* xr = x + (size_t)row * DIM;
    int tid = threadIdx.x;
    __shared__ float sx[DIM];
    float v0 = xr[tid], v1 = xr[tid + 256];
    float s = v0 + v1, q = v0*v0 + v1*v1;
    __shared__ float ss[8], sq[8];
    for (int o = 16; o; o >>= 1){ s += __shfl_down_sync(~0u, s, o); q += __shfl_down_sync(~0u, q, o); }
    if ((tid & 31) == 0){ ss[tid >> 5] = s; sq[tid >> 5] = q; }
    __syncthreads();
    __shared__ float mean_s, rstd_s;
    if (tid == 0){
        float S = 0.f, Q = 0.f;
        #pragma unroll
        for (int i = 0; i < 8; i++){ S += ss[i]; Q += sq[i]; }
        float m = S * (1.f/DIM);
        float var = Q * (1.f/DIM) - m*m;
        mean_s = m; rstd_s = rsqrtf(var + 1e-5f);
    }
    __syncthreads();
    float m = mean_s, rr = rstd_s;
    sx[tid]       = (v0 - m)*rr*w[tid]       + b[tid];
    sx[tid + 256] = (v1 - m)*rr*w[tid + 256] + b[tid + 256];
    __syncthreads();
    if (tid < 128){
        int j = tid;
        float x0 = sx[j], x1 = sx[j+128], x2 = sx[j+256], x3 = sx[j+384];
        float* qq = g_fr + (size_t)row * 1024 + j;
        qq[0]   = x0 + x1 + x2 + x3;  qq[128] = 0.f;
        qq[256] = x0 - x2;            qq[384] = -(x1 - x3);
        qq[512] = x0 - x1 + x2 - x3;  qq[640] = 0.f;
        qq[768] = x0 - x2;            qq[896] = x1 - x3;
    }
}

// ---------------- causal depthwise conv + silu -> bf16 ----------------
__global__ void k_conv_silu(const float* __restrict__ conv_w, const float* __restrict__ conv_b){
    int idx = blockIdx.x * blockDim.x + threadIdx.x;
    if (idx >= ROWS * DI) return;
    int c = idx & (DI - 1);
    int l = (idx >> 10) & (LSEQ - 1);
    int b = idx >> 20;
    const float* xm = g_xz + (size_t)b * LSEQ * (2*DI);
    float acc = conv_b[c];
    #pragma unroll
    for (int k = 0; k < DC; k++){
        int lp = l + k - (DC - 1);
        if (lp >= 0) acc = fmaf(conv_w[c*DC + k], xm[(size_t)lp*(2*DI) + c], acc);
    }
    g_xmch[idx] = __float2bfloat16_rn(silu_f(acc));
}

// ---------------- selective scan + fused gate ----------------
#define SC_LT 16
__global__ void __launch_bounds__(256) k_scan2(const float* __restrict__ A_log,
                                               const float* __restrict__ Dv){
    __shared__ float sdt[SC_LT][8], su[SC_LT][8];
    __shared__ float sB[SC_LT][64], sC[SC_LT][64];
    __shared__ float sy[SC_LT][8];
    const int tid = threadIdx.x, w = tid >> 5, lane = tid & 31;
    const int b = blockIdx.x >> 7;
    const int dblk = blockIdx.x & 127;
    const int d0 = dblk * 8;
    const int d = d0 + w;
    const float A0 = -__expf(A_log[d*DS + lane]);
    const float A1 = -__expf(A_log[d*DS + 32 + lane]);
    const float* pdt = g_dt + (size_t)b*LSEQ*DI;
    const __nv_bfloat16* puh = g_xmch + (size_t)b*LSEQ*DI;
    const float* pp  = g_proj + (size_t)b*LSEQ*256;
    const float* pz  = g_xz   + (size_t)b*LSEQ*(2*DI) + DI;
    __nv_bfloat16* py = g_yh  + (size_t)b*LSEQ*DI;
    float h0 = 0.f, h1 = 0.f;
    for (int l0 = 0; l0 < LSEQ; l0 += SC_LT){
        if (tid < SC_LT*8){
            int s = tid >> 3, j = tid & 7;
            sdt[s][j] = pdt[(size_t)(l0+s)*DI + d0 + j];
            su [s][j] = __bfloat162float(puh[(size_t)(l0+s)*DI + d0 + j]);
        }
        {
            int s = tid >> 4, j4 = tid & 15;
            const float* pr = pp + (size_t)(l0+s)*256;
            *(float4*)&sB[s][j4*4] = *(const float4*)(pr + 32 + j4*4);
            *(float4*)&sC[s][j4*4] = *(const float4*)(pr + 96 + j4*4);
        }
        __syncthreads();
        float dA0[SC_LT], dA1[SC_LT], du[SC_LT];
        #pragma unroll
        for (int s = 0; s < SC_LT; s++){
            float dtv = sdt[s][w];
            dA0[s] = __expf(dtv*A0);
            dA1[s] = __expf(dtv*A1);
            du[s]  = dtv * su[s][w];
        }
        #pragma unroll
        for (int half = 0; half < 2; half++){
            float hs0[8], hs1[8];
            #pragma unroll
            for (int t = 0; t < 8; t++){
                int s = half*8 + t;
                h0 = fmaf(dA0[s], h0, du[s]*sB[s][lane]);
                h1 = fmaf(dA1[s], h1, du[s]*sB[s][lane+32]);
                hs0[t] = h0; hs1[t] = h1;
            }
            #pragma unroll
            for (int t = 0; t < 8; t++){
                int s = half*8 + t;
                float yv = hs0[t]*sC[s][lane] + hs1[t]*sC[s][lane+32];
                #pragma unroll
                for (int o = 16; o; o >>= 1) yv += __shfl_down_sync(~0u, yv, o);
                if (lane == 0) sy[s][w] = yv;
            }
        }
        __syncthreads();
        if (tid < SC_LT*8){
            int s = tid >> 3, j = tid & 7;
            size_t off = (size_t)(l0+s)*DI + d0 + j;
            float z = pz[(size_t)(l0+s)*(2*DI) + d0 + j];
            float y = fmaf(su[s][j], Dv[d0+j], sy[s][j]);
            py[off] = __float2bfloat16_rn(y * silu_f(z));
        }
        __syncthreads();
    }
}

// ---------------- build EinFFT real-GEMM weights/biases ----------------
__global__ void k_build(const float* __restrict__ cw1, const float* __restrict__ cw2,
                        const float* __restrict__ cb1, const float* __restrict__ cb2){
    int idx = blockIdx.x * blockDim.x + threadIdx.x;
    if (idx >= 4*256*256) return;
    int k = idx & 255, n = (idx >> 8) & 255, b = idx >> 16;
    int j = n & 127, d = k & 127;
    bool nre = n < 128, kre = k < 128;
    float w0a = cw1[b*16384 + d*128 + j];
    float w1a = cw1[65536 + b*16384 + d*128 + j];
    g_W1[idx] = nre ? (kre ? w0a : -w1a) : (kre ? w1a : w0a);
    float w0b = cw2[b*16384 + d*128 + j];
    float w1b = cw2[65536 + b*16384 + d*128 + j];
    g_W2[idx] = nre ? (kre ? w0b : -w1b) : (kre ? w1b : w0b);
    if (k == 0){
        g_b1[b*256 + n] = nre ? cb1[b*128 + j] : cb1[512 + b*128 + j];
        g_b2[b*256 + n] = nre ? cb2[b*128 + j] : cb2[512 + b*128 + j];
    }
}

// ---------------- 1024-pt radix-4 FFT along N, 4 columns/block (256 CTAs) ----------------
__global__ void k_fft1024r4(float sign){
    extern __shared__ float2 shm[];
    float2* tw = shm;
    float2* sh = shm + 1024;
    const int tid = threadIdx.x; // 512
    int blk = blockIdx.x;
    int b = blk >> 7;
    int rem = blk & 127;
    int kblk = rem >> 5, j4 = rem & 31;
    float* base = g_fr + (size_t)b * 1024 * 1024 + kblk*256 + j4*4;

    #pragma unroll
    for (int r = 0; r < 2; r++){
        int i = tid + r*512;
        float s, cc;
        sincosf(sign * 6.283185307179586f * (float)i / 1024.f, &s, &cc);
        tw[i] = make_float2(cc, s);
    }

    #pragma unroll
    for (int r = 0; r < 2; r++){
        int n = tid + r*512;
        int rv = ((n & 3) << 8) | (((n >> 2) & 3) << 6) | (((n >> 4) & 3) << 4)
               | (((n >> 6) & 3) << 2) | ((n >> 8) & 3);
        float4 re = *(const float4*)(base + (size_t)n*1024);
        float4 im = *(const float4*)(base + (size_t)n*1024 + 128);
        sh[0*1025 + rv] = make_float2(re.x, im.x);
        sh[1*1025 + rv] = make_float2(re.y, im.y);
        sh[2*1025 + rv] = make_float2(re.z, im.z);
        sh[3*1025 + rv] = make_float2(re.w, im.w);
    }
    __syncthreads();

    const int c = tid & 3, bf0 = tid >> 2;
    float2* S = sh + c*1025;
    #pragma unroll
    for (int st = 0; st < 5; st++){
        const int q = 1 << (2*st);
        const int tsh = 8 - 2*st;
        #pragma unroll
        for (int r = 0; r < 2; r++){
            int bf = bf0 + r*128;
            int j = bf & (q - 1);
            int i1 = ((bf & ~(q - 1)) << 2) | j;
            float2 x0 = S[i1], x1 = S[i1+q], x2 = S[i1+2*q], x3 = S[i1+3*q];
            if (st > 0){
                int j1 = j << tsh;
                x1 = cmulf(x1, tw[j1]);
                x2 = cmulf(x2, tw[2*j1]);
                x3 = cmulf(x3, tw[3*j1]);
            }
            float2 t0 = cadd(x0, x2), t1 = csub(x0, x2);
            float2 t2 = cadd(x1, x3), t3 = csub(x1, x3);
            float2 t3r = make_float2(-sign*t3.y, sign*t3.x);
            S[i1]       = cadd(t0, t2);
            S[i1+q]     = cadd(t1, t3r);
            S[i1+2*q]   = csub(t0, t2);
            S[i1+3*q]   = csub(t1, t3r);
        }
        __syncthreads();
    }

    const float sc = 0.015625f;
    #pragma unroll
    for (int r = 0; r < 2; r++){
        int n = tid + r*512;
        float2 v0 = sh[0*1025 + n], v1 = sh[1*1025 + n];
        float2 v2 = sh[2*1025 + n], v3 = sh[3*1025 + n];
        *(float4*)(base + (size_t)n*1024)       = make_float4(v0.x*sc, v1.x*sc, v2.x*sc, v3.x*sc);
        *(float4*)(base + (size_t)n*1024 + 128) = make_float4(v0.y*sc, v1.y*sc, v2.y*sc, v3.y*sc);
    }
}
#define FFT_SMEM ((1024 + 4*1025) * 8)

// ---------------- inverse 4-point DFT along NB, real part, add into out ----------------
__global__ void k_fft4_inv_add(float* __restrict__ out){
    int idx = blockIdx.x * blockDim.x + threadIdx.x;
    if (idx >= ROWS * 128) return;
    int j = idx & 127, row = idx >> 7;
    const float* q = g_fr + (size_t)row * 1024 + j;
    float r0 = q[0];
    float r1 = q[256], i1 = q[384];
    float r2 = q[512];
    float r3 = q[768], i3 = q[896];
    float* o = out + (size_t)row * DIM + j;
    o[0]   += r0 + r1 + r2 + r3;
    o[128] += r0 - i1 - r2 + i3;
    o[256] += r0 - r1 + r2 - r3;
    o[384] += r0 + i1 - r2 - i3;
}

// ---------------- host launch ----------------
extern "C" void kernel_launch(void* const* d_in, const int* in_sizes, int n_in,
                              void* d_out, int out_size){
    const float* x_in      = (const float*)d_in[0];
    const float* ln_w      = (const float*)d_in[1];
    const float* ln_b      = (const float*)d_in[2];
    const float* in_proj_w = (const float*)d_in[3];
    const float* conv_w    = (const float*)d_in[4];
    const float* conv_b    = (const float*)d_in[5];
    const float* x_proj_w  = (const float*)d_in[6];
    const float* dt_proj_w = (const float*)d_in[7];
    const float* dt_proj_b = (const float*)d_in[8];
    const float* A_log     = (const float*)d_in[9];
    const float* Dv        = (const float*)d_in[10];
    const float* out_proj_w= (const float*)d_in[11];
    const float* norm2_w   = (const float*)d_in[12];
    const float* norm2_b   = (const float*)d_in[13];
    const float* cw1       = (const float*)d_in[14];
    const float* cw2       = (const float*)d_in[15];
    const float* cb1       = (const float*)d_in[16];
    const float* cb2       = (const float*)d_in[17];
    float* xout = (float*)d_out;

    float *p_xz, *p_proj, *p_dt, *p_fr, *p_b1, *p_b2;
    __nv_bfloat16 *p_lnh, *p_xmch, *p_yh, *p_r1h, *p_wie, *p_woe, *p_wde, *p_w1e, *p_w2e, *p_xpe;
    cudaGetSymbolAddress((void**)&p_xz,    g_xz);
    cudaGetSymbolAddress((void**)&p_proj,  g_proj);
    cudaGetSymbolAddress((void**)&p_dt,    g_dt);
    cudaGetSymbolAddress((void**)&p_fr,    g_fr);
    cudaGetSymbolAddress((void**)&p_b1,    g_b1);
    cudaGetSymbolAddress((void**)&p_b2,    g_b2);
    cudaGetSymbolAddress((void**)&p_lnh,   g_lnh);
    cudaGetSymbolAddress((void**)&p_xmch,  g_xmch);
    cudaGetSymbolAddress((void**)&p_yh,    g_yh);
    cudaGetSymbolAddress((void**)&p_r1h,   g_r1h);
    cudaGetSymbolAddress((void**)&p_wie,   g_wie);
    cudaGetSymbolAddress((void**)&p_woe,   g_woe);
    cudaGetSymbolAddress((void**)&p_wde,   g_wde);
    cudaGetSymbolAddress((void**)&p_w1e,   g_w1e);
    cudaGetSymbolAddress((void**)&p_w2e,   g_w2e);
    cudaGetSymbolAddress((void**)&p_xpe,   g_xpe);

    cudaFuncSetAttribute(k_fft1024r4, cudaFuncAttributeMaxDynamicSharedMemorySize, FFT_SMEM);

    cudaMemcpyAsync(xout, x_in, (size_t)ROWS*DIM*sizeof(float), cudaMemcpyDeviceToDevice, 0);

    k_build<<<(4*256*256 + 255)/256, 256>>>(cw1, cw2, cb1, cb2);
    k_wext_all<<<(WN_TOT + 255)/256, 256>>>(in_proj_w, out_proj_w, dt_proj_w, x_proj_w);

    for (int blk = 0; blk < 2; blk++){
        // ---- Mamba ----
        k_layernorm<<<ROWS, 256>>>(xout, ln_w, ln_b, p_lnh);
        k_hgemm<0,4,4,1,0><<<dim3(16,16,1), 256>>>(512,
            p_lnh, DIM, 0, p_wie, 512, 0, p_xz, 2*DI, 0, nullptr, 0);
        k_conv_silu<<<(ROWS*DI + 255)/256, 256>>>(conv_w, conv_b);
        k_hgemm<0,1,2,1,0><<<dim3(4,64,1), 256>>>(1024,
            p_xmch, DI, 0, p_xpe, 1024, 0, p_proj, 256, 0, nullptr, 0);
        k_hgemm<1,2,4,0,0><<<dim3(8,32,1), 256>>>(32,
            p_proj, 256, 0, p_wde, 32, 0, p_dt, DI, 0, dt_proj_b, 0);
        k_scan2<<<256, 256>>>(A_log, Dv);
        k_hgemm<2,2,2,1,0><<<dim3(8,32,1), 256>>>(1024,
            p_yh, DI, 0, p_woe, 1024, 0, xout, DIM, 0, nullptr, 0);

        // ---- EinFFT ----
        k_layernorm_fft<<<ROWS, 256>>>(xout, norm2_w, norm2_b);
        k_fft1024r4<<<256, 512, FFT_SMEM>>>(-1.f);
        k_hgemm<3,2,2,0,1><<<dim3(4,32,4), 256>>>(256,
            p_fr, 1024, 256, p_w1e, 256, 256*256, p_r1h, 1024, 256, p_b1, 256);
        k_hgemm<4,2,2,1,0><<<dim3(4,32,4), 256>>>(256,
            p_r1h, 1024, 256, p_w2e, 256, 256*256, p_fr, 1024, 256, p_b2, 256);
        k_fft1024r4<<<256, 512, FFT_SMEM>>>(1.f);
        k_fft4_inv_add<<<(ROWS*128 + 255)/256, 256>>>(xout);
    }
}

// round 15
// speedup vs baseline: 1.1166x; 1.0085x over previous
#include <cuda_runtime.h>
#include <cuda_bf16.h>
#include <math.h>
#include <stdint.h>

// ---------------- problem constants ----------------
#define BSZ   2
#define LSEQ  1024
#define DIM   512
#define DI    1024
#define DS    64
#define DTR   32
#define DC    4
#define ROWS  (BSZ*LSEQ)    // 2048
#define LAMB  0.01f

typedef unsigned long long u64;

// ---------------- scratch ----------------
__device__ float  g_xz  [ROWS*2*DI];
__device__ float  g_proj[ROWS*256];
__device__ float  g_dt  [ROWS*DI];
__device__ float  g_fr  [ROWS*1024];
__device__ float  g_W1  [4*256*256];
__device__ float  g_W2  [4*256*256];
__device__ float  g_b1  [4*256];
__device__ float  g_b2  [4*256];
// bf16 activations
__device__ __nv_bfloat16 g_lnh [ROWS*DIM];
__device__ __nv_bfloat16 g_xmch[ROWS*DI];
__device__ __nv_bfloat16 g_yh  [ROWS*DI];
__device__ __nv_bfloat16 g_r1h [ROWS*1024];
// bf16 weights
__device__ __nv_bfloat16 g_wie[2048*512];
__device__ __nv_bfloat16 g_woe[512*1024];
__device__ __nv_bfloat16 g_wde[1024*32];
__device__ __nv_bfloat16 g_w1e[4*256*256];
__device__ __nv_bfloat16 g_w2e[4*256*256];
__device__ __nv_bfloat16 g_xpe[256*1024];

__device__ __forceinline__ float silu_f(float x){ return x / (1.f + expf(-x)); }
__device__ __forceinline__ float softplus_f(float x){ return x > 20.f ? x : log1pf(expf(x)); }
__device__ __forceinline__ float shrink_f(float x){
    return x > LAMB ? x - LAMB : (x < -LAMB ? x + LAMB : 0.f);
}

// ---------------- complex helpers ----------------
__device__ __forceinline__ float2 cadd(float2 a, float2 b){ return make_float2(a.x+b.x, a.y+b.y); }
__device__ __forceinline__ float2 csub(float2 a, float2 b){ return make_float2(a.x-b.x, a.y-b.y); }
__device__ __forceinline__ float2 cmulf(float2 a, float2 b){
    return make_float2(a.x*b.x - a.y*b.y, a.x*b.y + a.y*b.x);
}

// ---------------- mma / async helpers ----------------
__device__ __forceinline__ uint32_t s2u(const void* p){
    uint32_t a;
    asm("{ .reg .u64 t; cvta.to.shared.u64 t, %1; cvt.u32.u64 %0, t; }" : "=r"(a) : "l"(p));
    return a;
}
__device__ __forceinline__ void ldsm4(uint32_t* r, uint32_t addr){
    asm volatile("ldmatrix.sync.aligned.m8n8.x4.shared.b16 {%0,%1,%2,%3}, [%4];"
        : "=r"(r[0]), "=r"(r[1]), "=r"(r[2]), "=r"(r[3]) : "r"(addr));
}
__device__ __forceinline__ void mma_bf16(float* c, const uint32_t* a, const uint32_t* b){
    asm volatile("mma.sync.aligned.m16n8k16.row.col.f32.bf16.bf16.f32 "
        "{%0,%1,%2,%3}, {%4,%5,%6,%7}, {%8,%9}, {%0,%1,%2,%3};"
        : "+f"(c[0]), "+f"(c[1]), "+f"(c[2]), "+f"(c[3])
        : "r"(a[0]), "r"(a[1]), "r"(a[2]), "r"(a[3]), "r"(b[0]), "r"(b[1]));
}
__device__ __forceinline__ void cpa16(uint32_t dst, const void* src){
    asm volatile("cp.async.cg.shared.global [%0], [%1], 16;" :: "r"(dst), "l"(src));
}
#define CPA_COMMIT asm volatile("cp.async.commit_group;" ::: "memory")
#define CPA_WAIT0  asm volatile("cp.async.wait_group 0;" ::: "memory")

__device__ __forceinline__ uint4 cvt8(float4 v0, float4 v1){
    union { uint4 u; __nv_bfloat162 h[4]; } r;
    r.h[0] = __floats2bfloat162_rn(v0.x, v0.y);
    r.h[1] = __floats2bfloat162_rn(v0.z, v0.w);
    r.h[2] = __floats2bfloat162_rn(v1.x, v1.y);
    r.h[3] = __floats2bfloat162_rn(v1.z, v1.w);
    return r.u;
}
__device__ __forceinline__ uint2 cvt4(float4 v0){
    union { uint2 u; __nv_bfloat162 h[2]; } r;
    r.h[0] = __floats2bfloat162_rn(v0.x, v0.y);
    r.h[1] = __floats2bfloat162_rn(v0.z, v0.w);
    return r.u;
}

// ---------------- tensor-core bf16 GEMM with cp.async pipeline ----------------
// C[M,N] = A[M,K] @ B[N,K]^T ; BM=32*MI, BN=32*NI, chunk=32 K, 256 thr (8 warps 2x4),
// double-buffered smem, cp.async for B always and A when ABF=1.
// EPI: 0 store, 1 softplus(+bias), 2 +=, 3 relu(+bias), 4 softshrink(+bias)
template<int EPI, int MI, int NI, int ABF, int CBF>
__global__ void __launch_bounds__(256,2)
k_hgemm(int K,
        const void* __restrict__ Av, int lda, long long sAz,
        const __nv_bfloat16* __restrict__ Bw, int ldb, long long sBz,
        void* __restrict__ Cv, int ldc, long long sCz,
        const float* __restrict__ bias, long long sbz)
{
    constexpr int BM = 32*MI, BN = 32*NI;
    constexpr int PITCH = 40;                  // bf16 elems per smem row (80 B)
    __shared__ __align__(16) __nv_bfloat16 As[2][BM][PITCH];
    __shared__ __align__(16) __nv_bfloat16 Bs[2][BN][PITCH];
    const int tid = threadIdx.x, lane = tid & 31, wid = tid >> 5;
    const int wy = wid >> 2, wx = wid & 3;
    const int m0 = blockIdx.y * BM, n0 = blockIdx.x * BN;
    const float* Af = (const float*)Av + blockIdx.z * sAz;
    const __nv_bfloat16* Ah = (const __nv_bfloat16*)Av + blockIdx.z * sAz;
    Bw += blockIdx.z * sBz;
    if (EPI == 1 || EPI == 3 || EPI == 4) bias += blockIdx.z * sbz;

    float acc[MI][NI][4] = {};
    const uint32_t sA = s2u(&As[0][0][0]), sB = s2u(&Bs[0][0][0]);
    const uint32_t strA = BM*PITCH*2, strB = BN*PITCH*2;

    // fp32-A register path mapping (ABF==0)
    const int arow = (MI == 4) ? (tid >> 1) : (MI == 2 ? (tid >> 2) : (tid >> 3));
    const int aq   = (MI == 4) ? ((tid & 1) * 16) : (MI == 2 ? ((tid & 3) * 8) : ((tid & 7) * 4));
    const int nch = K >> 5;

    // stage helpers
    auto stageB = [&](int buf, int k0){
        #pragma unroll
        for (int l = 0; l < (BN*4 + 255)/256; l++){
            int e = tid + l*256;
            if (BN*4 < 256 && e >= BN*4) break;
            int row = e >> 2, qo = (e & 3) * 8;
            cpa16(sB + buf*strB + (uint32_t)(row*PITCH + qo)*2,
                  Bw + (size_t)(n0+row)*ldb + k0 + qo);
        }
    };
    auto stageAh = [&](int buf, int k0){
        #pragma unroll
        for (int l = 0; l < (BM*4 + 255)/256; l++){
            int e = tid + l*256;
            if (BM*4 < 256 && e >= BM*4) break;
            int row = e >> 2, qo = (e & 3) * 8;
            cpa16(sA + buf*strA + (uint32_t)(row*PITCH + qo)*2,
                  Ah + (size_t)(m0+row)*lda + k0 + qo);
        }
    };

    // prologue: stage chunk 0 into buffer 0
    stageB(0, 0);
    if (ABF == 1){
        stageAh(0, 0);
    } else {
        float4 pa[MI];
        const float* ap = Af + (size_t)(m0+arow)*lda + aq;
        #pragma unroll
        for (int i = 0; i < MI; i++) pa[i] = *(const float4*)(ap + 4*i);
        if (MI == 1) *(uint2*)&As[0][arow][aq] = cvt4(pa[0]);
        else { *(uint4*)&As[0][arow][aq] = cvt8(pa[0], pa[1]);
               if (MI == 4) *(uint4*)&As[0][arow][aq+8] = cvt8(pa[2], pa[3]); }
    }
    CPA_COMMIT;
    CPA_WAIT0;
    __syncthreads();

    const int q = lane >> 3, r = lane & 7;

    for (int ch = 0; ch < nch; ch++){
        const int cur = ch & 1, nxt = cur ^ 1;
        float4 pa[MI];
        const bool more = (ch + 1 < nch);
        if (more){
            int k0 = (ch+1) * 32;
            stageB(nxt, k0);
            if (ABF == 1) stageAh(nxt, k0);
            else {
                const float* ap = Af + (size_t)(m0+arow)*lda + k0 + aq;
                #pragma unroll
                for (int i = 0; i < MI; i++) pa[i] = *(const float4*)(ap + 4*i);
            }
            CPA_COMMIT;
        }
        #pragma unroll
        for (int ks = 0; ks < 2; ks++){
            uint32_t af[MI][4], bf2[NI/2][4];
            #pragma unroll
            for (int mi = 0; mi < MI; mi++){
                int row = wy*(MI*16) + mi*16 + r + (q & 1)*8;
                int col = ks*16 + (q >> 1)*8;
                ldsm4(af[mi], sA + cur*strA + (uint32_t)(row*PITCH + col)*2);
            }
            #pragma unroll
            for (int nb = 0; nb < NI/2; nb++){
                int nrow = wx*(8*NI) + nb*16 + r + (q >> 1)*8;
                int ncol = ks*16 + (q & 1)*8;
                ldsm4(bf2[nb], sB + cur*strB + (uint32_t)(nrow*PITCH + ncol)*2);
            }
            #pragma unroll
            for (int mi = 0; mi < MI; mi++)
                #pragma unroll
                for (int ni = 0; ni < NI; ni++)
                    mma_bf16(acc[mi][ni], af[mi], &bf2[ni>>1][(ni&1)*2]);
        }
        if (more){
            if (ABF == 0){
                if (MI == 1) *(uint2*)&As[nxt][arow][aq] = cvt4(pa[0]);
                else { *(uint4*)&As[nxt][arow][aq] = cvt8(pa[0], pa[1]);
                       if (MI == 4) *(uint4*)&As[nxt][arow][aq+8] = cvt8(pa[2], pa[3]); }
            }
            CPA_WAIT0;
            __syncthreads();
        }
    }

    float* Cf = (float*)Cv + blockIdx.z * sCz;
    __nv_bfloat16* Ch = (__nv_bfloat16*)Cv + blockIdx.z * sCz;
    #pragma unroll
    for (int mi = 0; mi < MI; mi++){
        #pragma unroll
        for (int ni = 0; ni < NI; ni++){
            int row = m0 + wy*(MI*16) + mi*16 + (lane >> 2);
            int col = n0 + wx*(8*NI) + ni*8 + (lane & 3)*2;
            #pragma unroll
            for (int h = 0; h < 2; h++){
                float2 v = make_float2(acc[mi][ni][2*h], acc[mi][ni][2*h+1]);
                size_t off = (size_t)(row + h*8)*ldc + col;
                if (EPI == 1){
                    v.x = softplus_f(v.x + bias[col]);
                    v.y = softplus_f(v.y + bias[col+1]);
                } else if (EPI == 2){
                    float2 o = *(const float2*)(Cf + off);
                    v.x += o.x; v.y += o.y;
                } else if (EPI == 3){
                    v.x = fmaxf(v.x + bias[col], 0.f);
                    v.y = fmaxf(v.y + bias[col+1], 0.f);
                } else if (EPI == 4){
                    v.x = shrink_f(v.x + bias[col]);
                    v.y = shrink_f(v.y + bias[col+1]);
                }
                if (CBF) *(__nv_bfloat162*)(Ch + off) = __floats2bfloat162_rn(v.x, v.y);
                else     *(float2*)(Cf + off) = v;
            }
        }
    }
}

// ---------------- fused weight conversion ----------------
#define WN_IE  (2048*512)
#define WN_OE  (512*1024)
#define WN_DE  (1024*32)
#define WN_W1  (4*256*256)
#define WN_W2  (4*256*256)
#define WN_XP  (256*1024)
#define WN_TOT (WN_IE+WN_OE+WN_DE+WN_W1+WN_W2+WN_XP)
__global__ void k_wext_all(const float* __restrict__ in_proj_w,
                           const float* __restrict__ out_proj_w,
                           const float* __restrict__ dt_proj_w,
                           const float* __restrict__ x_proj_w){
    int idx = blockIdx.x * blockDim.x + threadIdx.x;
    if (idx >= WN_TOT) return;
    float x; __nv_bfloat16* dst; int local;
    if (idx < WN_IE){ local = idx; x = in_proj_w[local]; dst = g_wie; }
    else if (idx < WN_IE+WN_OE){ local = idx - WN_IE; x = out_proj_w[local]; dst = g_woe; }
    else if (idx < WN_IE+WN_OE+WN_DE){ local = idx - WN_IE-WN_OE; x = dt_proj_w[local]; dst = g_wde; }
    else if (idx < WN_IE+WN_OE+WN_DE+WN_W1){ local = idx - WN_IE-WN_OE-WN_DE; x = g_W1[local]; dst = g_w1e; }
    else if (idx < WN_IE+WN_OE+WN_DE+WN_W1+WN_W2){ local = idx - WN_IE-WN_OE-WN_DE-WN_W1; x = g_W2[local]; dst = g_w2e; }
    else {
        local = idx - WN_IE-WN_OE-WN_DE-WN_W1-WN_W2;
        int n = local >> 10, k = local & 1023;
        x = (n < 160) ? x_proj_w[n*1024 + k] : 0.f;
        dst = g_xpe;
    }
    dst[local] = __float2bfloat16_rn(x);
}

// ---------------- layernorm -> bf16 ----------------
__global__ void k_layernorm(const float* __restrict__ x, const float* __restrict__ w,
                            const float* __restrict__ b, __nv_bfloat16* __restrict__ out){
    int row = blockIdx.x;
    const float* xr = x + (size_t)row * DIM;
    int tid = threadIdx.x;
    float v0 = xr[tid], v1 = xr[tid + 256];
    float s = v0 + v1, q = v0*v0 + v1*v1;
    __shared__ float ss[8], sq[8];
    for (int o = 16; o; o >>= 1){ s += __shfl_down_sync(~0u, s, o); q += __shfl_down_sync(~0u, q, o); }
    if ((tid & 31) == 0){ ss[tid >> 5] = s; sq[tid >> 5] = q; }
    __syncthreads();
    __shared__ float mean_s, rstd_s;
    if (tid == 0){
        float S = 0.f, Q = 0.f;
        #pragma unroll
        for (int i = 0; i < 8; i++){ S += ss[i]; Q += sq[i]; }
        float m = S * (1.f/DIM);
        float var = Q * (1.f/DIM) - m*m;
        mean_s = m; rstd_s = rsqrtf(var + 1e-5f);
    }
    __syncthreads();
    float m = mean_s, rr = rstd_s;
    out[(size_t)row*DIM + tid]       = __float2bfloat16_rn((v0 - m)*rr*w[tid]       + b[tid]);
    out[(size_t)row*DIM + tid + 256] = __float2bfloat16_rn((v1 - m)*rr*w[tid + 256] + b[tid + 256]);
}

// ---------------- fused layernorm + forward DFT-4 ----------------
__global__ void k_layernorm_fft(const float* __restrict__ x, const float* __restrict__ w,
                                const float* __restrict__ b){
    int row = blockIdx.x;
    const float* xr = x + (size_t)row * DIM;
    int tid = threadIdx.x;
    __shared__ float sx[DIM];
    float v0 = xr[tid], v1 = xr[tid + 256];
    float s = v0 + v1, q = v0*v0 + v1*v1;
    __shared__ float ss[8], sq[8];
    for (int o = 16; o; o >>= 1){ s += __shfl_down_sync(~0u, s, o); q += __shfl_down_sync(~0u, q, o); }
    if ((tid & 31) == 0){ ss[tid >> 5] = s; sq[tid >> 5] = q; }
    __syncthreads();
    __shared__ float mean_s, rstd_s;
    if (tid == 0){
        float S = 0.f, Q = 0.f;
        #pragma unroll
        for (int i = 0; i < 8; i++){ S += ss[i]; Q += sq[i]; }
        float m = S * (1.f/DIM);
        float var = Q * (1.f/DIM) - m*m;
        mean_s = m; rstd_s = rsqrtf(var + 1e-5f);
    }
    __syncthreads();
    float m = mean_s, rr = rstd_s;
    sx[tid]       = (v0 - m)*rr*w[tid]       + b[tid];
    sx[tid + 256] = (v1 - m)*rr*w[tid + 256] + b[tid + 256];
    __syncthreads();
    if (tid < 128){
        int j = tid;
        float x0 = sx[j], x1 = sx[j+128], x2 = sx[j+256], x3 = sx[j+384];
        float* qq = g_fr + (size_t)row * 1024 + j;
        qq[0]   = x0 + x1 + x2 + x3;  qq[128] = 0.f;
        qq[256] = x0 - x2;            qq[384] = -(x1 - x3);
        qq[512] = x0 - x1 + x2 - x3;  qq[640] = 0.f;
        qq[768] = x0 - x2;            qq[896] = x1 - x3;
    }
}

// ---------------- causal depthwise conv + silu -> bf16 ----------------
__global__ void k_conv_silu(const float* __restrict__ conv_w, const float* __restrict__ conv_b){
    int idx = blockIdx.x * blockDim.x + threadIdx.x;
    if (idx >= ROWS * DI) return;
    int c = idx & (DI - 1);
    int l = (idx >> 10) & (LSEQ - 1);
    int b = idx >> 20;
    const float* xm = g_xz + (size_t)b * LSEQ * (2*DI);
    float acc = conv_b[c];
    #pragma unroll
    for (int k = 0; k < DC; k++){
        int lp = l + k - (DC - 1);
        if (lp >= 0) acc = fmaf(conv_w[c*DC + k], xm[(size_t)lp*(2*DI) + c], acc);
    }
    g_xmch[idx] = __float2bfloat16_rn(silu_f(acc));
}

// ---------------- selective scan + fused gate ----------------
#define SC_LT 16
__global__ void __launch_bounds__(256) k_scan2(const float* __restrict__ A_log,
                                               const float* __restrict__ Dv){
    __shared__ float sdt[SC_LT][8], su[SC_LT][8];
    __shared__ float sB[SC_LT][64], sC[SC_LT][64];
    __shared__ float sy[SC_LT][8];
    const int tid = threadIdx.x, w = tid >> 5, lane = tid & 31;
    const int b = blockIdx.x >> 7;
    const int dblk = blockIdx.x & 127;
    const int d0 = dblk * 8;
    const int d = d0 + w;
    const float A0 = -__expf(A_log[d*DS + lane]);
    const float A1 = -__expf(A_log[d*DS + 32 + lane]);
    const float* pdt = g_dt + (size_t)b*LSEQ*DI;
    const __nv_bfloat16* puh = g_xmch + (size_t)b*LSEQ*DI;
    const float* pp  = g_proj + (size_t)b*LSEQ*256;
    const float* pz  = g_xz   + (size_t)b*LSEQ*(2*DI) + DI;
    __nv_bfloat16* py = g_yh  + (size_t)b*LSEQ*DI;
    float h0 = 0.f, h1 = 0.f;
    for (int l0 = 0; l0 < LSEQ; l0 += SC_LT){
        if (tid < SC_LT*8){
            int s = tid >> 3, j = tid & 7;
            sdt[s][j] = pdt[(size_t)(l0+s)*DI + d0 + j];
            su [s][j] = __bfloat162float(puh[(size_t)(l0+s)*DI + d0 + j]);
        }
        {
            int s = tid >> 4, j4 = tid & 15;
            const float* pr = pp + (size_t)(l0+s)*256;
            *(float4*)&sB[s][j4*4] = *(const float4*)(pr + 32 + j4*4);
            *(float4*)&sC[s][j4*4] = *(const float4*)(pr + 96 + j4*4);
        }
        __syncthreads();
        float dA0[SC_LT], dA1[SC_LT], du[SC_LT];
        #pragma unroll
        for (int s = 0; s < SC_LT; s++){
            float dtv = sdt[s][w];
            dA0[s] = __expf(dtv*A0);
            dA1[s] = __expf(dtv*A1);
            du[s]  = dtv * su[s][w];
        }
        #pragma unroll
        for (int half = 0; half < 2; half++){
            float hs0[8], hs1[8];
            #pragma unroll
            for (int t = 0; t < 8; t++){
                int s = half*8 + t;
                h0 = fmaf(dA0[s], h0, du[s]*sB[s][lane]);
                h1 = fmaf(dA1[s], h1, du[s]*sB[s][lane+32]);
                hs0[t] = h0; hs1[t] = h1;
            }
            #pragma unroll
            for (int t = 0; t < 8; t++){
                int s = half*8 + t;
                float yv = hs0[t]*sC[s][lane] + hs1[t]*sC[s][lane+32];
                #pragma unroll
                for (int o = 16; o; o >>= 1) yv += __shfl_down_sync(~0u, yv, o);
                if (lane == 0) sy[s][w] = yv;
            }
        }
        __syncthreads();
        if (tid < SC_LT*8){
            int s = tid >> 3, j = tid & 7;
            size_t off = (size_t)(l0+s)*DI + d0 + j;
            float z = pz[(size_t)(l0+s)*(2*DI) + d0 + j];
            float y = fmaf(su[s][j], Dv[d0+j], sy[s][j]);
            py[off] = __float2bfloat16_rn(y * silu_f(z));
        }
        __syncthreads();
    }
}

// ---------------- build EinFFT real-GEMM weights/biases ----------------
__global__ void k_build(const float* __restrict__ cw1, const float* __restrict__ cw2,
                        const float* __restrict__ cb1, const float* __restrict__ cb2){
    int idx = blockIdx.x * blockDim.x + threadIdx.x;
    if (idx >= 4*256*256) return;
    int k = idx & 255, n = (idx >> 8) & 255, b = idx >> 16;
    int j = n & 127, d = k & 127;
    bool nre = n < 128, kre = k < 128;
    float w0a = cw1[b*16384 + d*128 + j];
    float w1a = cw1[65536 + b*16384 + d*128 + j];
    g_W1[idx] = nre ? (kre ? w0a : -w1a) : (kre ? w1a : w0a);
    float w0b = cw2[b*16384 + d*128 + j];
    float w1b = cw2[65536 + b*16384 + d*128 + j];
    g_W2[idx] = nre ? (kre ? w0b : -w1b) : (kre ? w1b : w0b);
    if (k == 0){
        g_b1[b*256 + n] = nre ? cb1[b*128 + j] : cb1[512 + b*128 + j];
        g_b2[b*256 + n] = nre ? cb2[b*128 + j] : cb2[512 + b*128 + j];
    }
}

// ---------------- 1024-pt radix-4 FFT along N, 4 columns/block (256 CTAs) ----------------
__global__ void k_fft1024r4(float sign){
    extern __shared__ float2 shm[];
    float2* tw = shm;
    float2* sh = shm + 1024;
    const int tid = threadIdx.x; // 512
    int blk = blockIdx.x;
    int b = blk >> 7;
    int rem = blk & 127;
    int kblk = rem >> 5, j4 = rem & 31;
    float* base = g_fr + (size_t)b * 1024 * 1024 + kblk*256 + j4*4;

    #pragma unroll
    for (int r = 0; r < 2; r++){
        int i = tid + r*512;
        float s, cc;
        sincosf(sign * 6.283185307179586f * (float)i / 1024.f, &s, &cc);
        tw[i] = make_float2(cc, s);
    }

    #pragma unroll
    for (int r = 0; r < 2; r++){
        int n = tid + r*512;
        int rv = ((n & 3) << 8) | (((n >> 2) & 3) << 6) | (((n >> 4) & 3) << 4)
               | (((n >> 6) & 3) << 2) | ((n >> 8) & 3);
        float4 re = *(const float4*)(base + (size_t)n*1024);
        float4 im = *(const float4*)(base + (size_t)n*1024 + 128);
        sh[0*1025 + rv] = make_float2(re.x, im.x);
        sh[1*1025 + rv] = make_float2(re.y, im.y);
        sh[2*1025 + rv] = make_float2(re.z, im.z);
        sh[3*1025 + rv] = make_float2(re.w, im.w);
    }
    __syncthreads();

    const int c = tid & 3, bf0 = tid >> 2;
    float2* S = sh + c*1025;
    #pragma unroll
    for (int st = 0; st < 5; st++){
        const int q = 1 << (2*st);
        const int tsh = 8 - 2*st;
        #pragma unroll
        for (int r = 0; r < 2; r++){
            int bf = bf0 + r*128;
            int j = bf & (q - 1);
            int i1 = ((bf & ~(q - 1)) << 2) | j;
            float2 x0 = S[i1], x1 = S[i1+q], x2 = S[i1+2*q], x3 = S[i1+3*q];
            if (st > 0){
                int j1 = j << tsh;
                x1 = cmulf(x1, tw[j1]);
                x2 = cmulf(x2, tw[2*j1]);
                x3 = cmulf(x3, tw[3*j1]);
            }
            float2 t0 = cadd(x0, x2), t1 = csub(x0, x2);
            float2 t2 = cadd(x1, x3), t3 = csub(x1, x3);
            float2 t3r = make_float2(-sign*t3.y, sign*t3.x);
            S[i1]       = cadd(t0, t2);
            S[i1+q]     = cadd(t1, t3r);
            S[i1+2*q]   = csub(t0, t2);
            S[i1+3*q]   = csub(t1, t3r);
        }
        __syncthreads();
    }

    const float sc = 0.015625f;
    #pragma unroll
    for (int r = 0; r < 2; r++){
        int n = tid + r*512;
        float2 v0 = sh[0*1025 + n], v1 = sh[1*1025 + n];
        float2 v2 = sh[2*1025 + n], v3 = sh[3*1025 + n];
        *(float4*)(base + (size_t)n*1024)       = make_float4(v0.x*sc, v1.x*sc, v2.x*sc, v3.x*sc);
        *(float4*)(base + (size_t)n*1024 + 128) = make_float4(v0.y*sc, v1.y*sc, v2.y*sc, v3.y*sc);
    }
}
#define FFT_SMEM ((1024 + 4*1025) * 8)

// ---------------- inverse 4-point DFT along NB, real part, add into out ----------------
__global__ void k_fft4_inv_add(float* __restrict__ out){
    int idx = blockIdx.x * blockDim.x + threadIdx.x;
    if (idx >= ROWS * 128) return;
    int j = idx & 127, row = idx >> 7;
    const float* q = g_fr + (size_t)row * 1024 + j;
    float r0 = q[0];
    float r1 = q[256], i1 = q[384];
    float r2 = q[512];
    float r3 = q[768], i3 = q[896];
    float* o = out + (size_t)row * DIM + j;
    o[0]   += r0 + r1 + r2 + r3;
    o[128] += r0 - i1 - r2 + i3;
    o[256] += r0 - r1 + r2 - r3;
    o[384] += r0 + i1 - r2 - i3;
}

// ---------------- host launch ----------------
extern "C" void kernel_launch(void* const* d_in, const int* in_sizes, int n_in,
                              void* d_out, int out_size){
    const float* x_in      = (const float*)d_in[0];
    const float* ln_w      = (const float*)d_in[1];
    const float* ln_b      = (const float*)d_in[2];
    const float* in_proj_w = (const float*)d_in[3];
    const float* conv_w    = (const float*)d_in[4];
    const float* conv_b    = (const float*)d_in[5];
    const float* x_proj_w  = (const float*)d_in[6];
    const float* dt_proj_w = (const float*)d_in[7];
    const float* dt_proj_b = (const float*)d_in[8];
    const float* A_log     = (const float*)d_in[9];
    const float* Dv        = (const float*)d_in[10];
    const float* out_proj_w= (const float*)d_in[11];
    const float* norm2_w   = (const float*)d_in[12];
    const float* norm2_b   = (const float*)d_in[13];
    const float* cw1       = (const float*)d_in[14];
    const float* cw2       = (const float*)d_in[15];
    const float* cb1       = (const float*)d_in[16];
    const float* cb2       = (const float*)d_in[17];
    float* xout = (float*)d_out;

    float *p_xz, *p_proj, *p_dt, *p_fr, *p_b1, *p_b2;
    __nv_bfloat16 *p_lnh, *p_xmch, *p_yh, *p_r1h, *p_wie, *p_woe, *p_wde, *p_w1e, *p_w2e, *p_xpe;
    cudaGetSymbolAddress((void**)&p_xz,    g_xz);
    cudaGetSymbolAddress((void**)&p_proj,  g_proj);
    cudaGetSymbolAddress((void**)&p_dt,    g_dt);
    cudaGetSymbolAddress((void**)&p_fr,    g_fr);
    cudaGetSymbolAddress((void**)&p_b1,    g_b1);
    cudaGetSymbolAddress((void**)&p_b2,    g_b2);
    cudaGetSymbolAddress((void**)&p_lnh,   g_lnh);
    cudaGetSymbolAddress((void**)&p_xmch,  g_xmch);
    cudaGetSymbolAddress((void**)&p_yh,    g_yh);
    cudaGetSymbolAddress((void**)&p_r1h,   g_r1h);
    cudaGetSymbolAddress((void**)&p_wie,   g_wie);
    cudaGetSymbolAddress((void**)&p_woe,   g_woe);
    cudaGetSymbolAddress((void**)&p_wde,   g_wde);
    cudaGetSymbolAddress((void**)&p_w1e,   g_w1e);
    cudaGetSymbolAddress((void**)&p_w2e,   g_w2e);
    cudaGetSymbolAddress((void**)&p_xpe,   g_xpe);

    cudaFuncSetAttribute(k_fft1024r4, cudaFuncAttributeMaxDynamicSharedMemorySize, FFT_SMEM);

    cudaMemcpyAsync(xout, x_in, (size_t)ROWS*DIM*sizeof(float), cudaMemcpyDeviceToDevice, 0);

    k_build<<<(4*256*256 + 255)/256, 256>>>(cw1, cw2, cb1, cb2);
    k_wext_all<<<(WN_TOT + 255)/256, 256>>>(in_proj_w, out_proj_w, dt_proj_w, x_proj_w);

    for (int blk = 0; blk < 2; blk++){
        // ---- Mamba ----
        k_layernorm<<<ROWS, 256>>>(xout, ln_w, ln_b, p_lnh);
        k_hgemm<0,2,4,1,0><<<dim3(16,32,1), 256>>>(512,
            p_lnh, DIM, 0, p_wie, 512, 0, p_xz, 2*DI, 0, nullptr, 0);
        k_conv_silu<<<(ROWS*DI + 255)/256, 256>>>(conv_w, conv_b);
        k_hgemm<0,1,2,1,0><<<dim3(4,64,1), 256>>>(1024,
            p_xmch, DI, 0, p_xpe, 1024, 0, p_proj, 256, 0, nullptr, 0);
        k_hgemm<1,2,4,0,0><<<dim3(8,32,1), 256>>>(32,
            p_proj, 256, 0, p_wde, 32, 0, p_dt, DI, 0, dt_proj_b, 0);
        k_scan2<<<256, 256>>>(A_log, Dv);
        k_hgemm<2,2,2,1,0><<<dim3(8,32,1), 256>>>(1024,
            p_yh, DI, 0, p_woe, 1024, 0, xout, DIM, 0, nullptr, 0);

        // ---- EinFFT ----
        k_layernorm_fft<<<ROWS, 256>>>(xout, norm2_w, norm2_b);
        k_fft1024r4<<<256, 512, FFT_SMEM>>>(-1.f);
        k_hgemm<3,2,2,0,1><<<dim3(4,32,4), 256>>>(256,
            p_fr, 1024, 256, p_w1e, 256, 256*256, p_r1h, 1024, 256, p_b1, 256);
        k_hgemm<4,2,2,1,0><<<dim3(4,32,4), 256>>>(256,
            p_r1h, 1024, 256, p_w2e, 256, 256*256, p_fr, 1024, 256, p_b2, 256);
        k_fft1024r4<<<256, 512, FFT_SMEM>>>(1.f);
        k_fft4_inv_add<<<(ROWS*128 + 255)/256, 256>>>(xout);
    }
}

// round 16
// speedup vs baseline: 1.1410x; 1.0218x over previous
#include <cuda_runtime.h>
#include <cuda_bf16.h>
#include <math.h>
#include <stdint.h>

// ---------------- problem constants ----------------
#define BSZ   2
#define LSEQ  1024
#define DIM   512
#define DI    1024
#define DS    64
#define DTR   32
#define DC    4
#define ROWS  (BSZ*LSEQ)    // 2048
#define LAMB  0.01f

typedef unsigned long long u64;

// ---------------- scratch ----------------
__device__ float  g_xz  [ROWS*2*DI];
__device__ float  g_proj[ROWS*256];
__device__ float  g_dt  [ROWS*DI];
__device__ float  g_fr  [ROWS*1024];
__device__ float  g_W1  [4*256*256];
__device__ float  g_W2  [4*256*256];
__device__ float  g_b1  [4*256];
__device__ float  g_b2  [4*256];
// bf16 activations
__device__ __nv_bfloat16 g_lnh [ROWS*DIM];
__device__ __nv_bfloat16 g_xmch[ROWS*DI];
__device__ __nv_bfloat16 g_yh  [ROWS*DI];
__device__ __nv_bfloat16 g_r1h [ROWS*1024];
// bf16 weights
__device__ __nv_bfloat16 g_wie[2048*512];
__device__ __nv_bfloat16 g_woe[512*1024];
__device__ __nv_bfloat16 g_wde[1024*32];
__device__ __nv_bfloat16 g_w1e[4*256*256];
__device__ __nv_bfloat16 g_w2e[4*256*256];
__device__ __nv_bfloat16 g_xpe[256*1024];

__device__ __forceinline__ float silu_f(float x){ return x / (1.f + expf(-x)); }
__device__ __forceinline__ float softplus_f(float x){ return x > 20.f ? x : log1pf(expf(x)); }
__device__ __forceinline__ float shrink_f(float x){
    return x > LAMB ? x - LAMB : (x < -LAMB ? x + LAMB : 0.f);
}

// ---------------- complex helpers ----------------
__device__ __forceinline__ float2 cadd(float2 a, float2 b){ return make_float2(a.x+b.x, a.y+b.y); }
__device__ __forceinline__ float2 csub(float2 a, float2 b){ return make_float2(a.x-b.x, a.y-b.y); }
__device__ __forceinline__ float2 cmulf(float2 a, float2 b){
    return make_float2(a.x*b.x - a.y*b.y, a.x*b.y + a.y*b.x);
}

// ---------------- mma / async helpers ----------------
__device__ __forceinline__ uint32_t s2u(const void* p){
    uint32_t a;
    asm("{ .reg .u64 t; cvta.to.shared.u64 t, %1; cvt.u32.u64 %0, t; }" : "=r"(a) : "l"(p));
    return a;
}
__device__ __forceinline__ void ldsm4(uint32_t* r, uint32_t addr){
    asm volatile("ldmatrix.sync.aligned.m8n8.x4.shared.b16 {%0,%1,%2,%3}, [%4];"
        : "=r"(r[0]), "=r"(r[1]), "=r"(r[2]), "=r"(r[3]) : "r"(addr));
}
__device__ __forceinline__ void mma_bf16(float* c, const uint32_t* a, const uint32_t* b){
    asm volatile("mma.sync.aligned.m16n8k16.row.col.f32.bf16.bf16.f32 "
        "{%0,%1,%2,%3}, {%4,%5,%6,%7}, {%8,%9}, {%0,%1,%2,%3};"
        : "+f"(c[0]), "+f"(c[1]), "+f"(c[2]), "+f"(c[3])
        : "r"(a[0]), "r"(a[1]), "r"(a[2]), "r"(a[3]), "r"(b[0]), "r"(b[1]));
}
__device__ __forceinline__ void cpa16(uint32_t dst, const void* src){
    asm volatile("cp.async.cg.shared.global [%0], [%1], 16;" :: "r"(dst), "l"(src));
}
#define CPA_COMMIT asm volatile("cp.async.commit_group;" ::: "memory")
#define CPA_WAIT0  asm volatile("cp.async.wait_group 0;" ::: "memory")

__device__ __forceinline__ uint4 cvt8(float4 v0, float4 v1){
    union { uint4 u; __nv_bfloat162 h[4]; } r;
    r.h[0] = __floats2bfloat162_rn(v0.x, v0.y);
    r.h[1] = __floats2bfloat162_rn(v0.z, v0.w);
    r.h[2] = __floats2bfloat162_rn(v1.x, v1.y);
    r.h[3] = __floats2bfloat162_rn(v1.z, v1.w);
    return r.u;
}
__device__ __forceinline__ uint2 cvt4(float4 v0){
    union { uint2 u; __nv_bfloat162 h[2]; } r;
    r.h[0] = __floats2bfloat162_rn(v0.x, v0.y);
    r.h[1] = __floats2bfloat162_rn(v0.z, v0.w);
    return r.u;
}

// ---------------- tensor-core bf16 GEMM with cp.async pipeline ----------------
// C[M,N] = A[M,K] @ B[N,K]^T ; BM=32*MI, BN=32*NI, chunk=32 K, 256 thr (8 warps 2x4),
// double-buffered smem, cp.async for B always and A when ABF=1.
// EPI: 0 store, 1 softplus(+bias), 2 +=, 3 relu(+bias), 4 softshrink(+bias)
template<int EPI, int MI, int NI, int ABF, int CBF>
__global__ void __launch_bounds__(256,2)
k_hgemm(int K,
        const void* __restrict__ Av, int lda, long long sAz,
        const __nv_bfloat16* __restrict__ Bw, int ldb, long long sBz,
        void* __restrict__ Cv, int ldc, long long sCz,
        const float* __restrict__ bias, long long sbz)
{
    constexpr int BM = 32*MI, BN = 32*NI;
    constexpr int PITCH = 40;
    __shared__ __align__(16) __nv_bfloat16 As[2][BM][PITCH];
    __shared__ __align__(16) __nv_bfloat16 Bs[2][BN][PITCH];
    const int tid = threadIdx.x, lane = tid & 31, wid = tid >> 5;
    const int wy = wid >> 2, wx = wid & 3;
    const int m0 = blockIdx.y * BM, n0 = blockIdx.x * BN;
    const float* Af = (const float*)Av + blockIdx.z * sAz;
    const __nv_bfloat16* Ah = (const __nv_bfloat16*)Av + blockIdx.z * sAz;
    Bw += blockIdx.z * sBz;
    if (EPI == 1 || EPI == 3 || EPI == 4) bias += blockIdx.z * sbz;

    float acc[MI][NI][4] = {};
    const uint32_t sA = s2u(&As[0][0][0]), sB = s2u(&Bs[0][0][0]);
    const uint32_t strA = BM*PITCH*2, strB = BN*PITCH*2;

    const int arow = (MI == 4) ? (tid >> 1) : (MI == 2 ? (tid >> 2) : (tid >> 3));
    const int aq   = (MI == 4) ? ((tid & 1) * 16) : (MI == 2 ? ((tid & 3) * 8) : ((tid & 7) * 4));
    const int nch = K >> 5;

    auto stageB = [&](int buf, int k0){
        #pragma unroll
        for (int l = 0; l < (BN*4 + 255)/256; l++){
            int e = tid + l*256;
            if (BN*4 < 256 && e >= BN*4) break;
            int row = e >> 2, qo = (e & 3) * 8;
            cpa16(sB + buf*strB + (uint32_t)(row*PITCH + qo)*2,
                  Bw + (size_t)(n0+row)*ldb + k0 + qo);
        }
    };
    auto stageAh = [&](int buf, int k0){
        #pragma unroll
        for (int l = 0; l < (BM*4 + 255)/256; l++){
            int e = tid + l*256;
            if (BM*4 < 256 && e >= BM*4) break;
            int row = e >> 2, qo = (e & 3) * 8;
            cpa16(sA + buf*strA + (uint32_t)(row*PITCH + qo)*2,
                  Ah + (size_t)(m0+row)*lda + k0 + qo);
        }
    };

    stageB(0, 0);
    if (ABF == 1){
        stageAh(0, 0);
    } else {
        float4 pa[MI];
        const float* ap = Af + (size_t)(m0+arow)*lda + aq;
        #pragma unroll
        for (int i = 0; i < MI; i++) pa[i] = *(const float4*)(ap + 4*i);
        if (MI == 1) *(uint2*)&As[0][arow][aq] = cvt4(pa[0]);
        else { *(uint4*)&As[0][arow][aq] = cvt8(pa[0], pa[1]);
               if (MI == 4) *(uint4*)&As[0][arow][aq+8] = cvt8(pa[2], pa[3]); }
    }
    CPA_COMMIT;
    CPA_WAIT0;
    __syncthreads();

    const int q = lane >> 3, r = lane & 7;

    for (int ch = 0; ch < nch; ch++){
        const int cur = ch & 1, nxt = cur ^ 1;
        float4 pa[MI];
        const bool more = (ch + 1 < nch);
        if (more){
            int k0 = (ch+1) * 32;
            stageB(nxt, k0);
            if (ABF == 1) stageAh(nxt, k0);
            else {
                const float* ap = Af + (size_t)(m0+arow)*lda + k0 + aq;
                #pragma unroll
                for (int i = 0; i < MI; i++) pa[i] = *(const float4*)(ap + 4*i);
            }
            CPA_COMMIT;
        }
        #pragma unroll
        for (int ks = 0; ks < 2; ks++){
            uint32_t af[MI][4], bf2[NI/2][4];
            #pragma unroll
            for (int mi = 0; mi < MI; mi++){
                int row = wy*(MI*16) + mi*16 + r + (q & 1)*8;
                int col = ks*16 + (q >> 1)*8;
                ldsm4(af[mi], sA + cur*strA + (uint32_t)(row*PITCH + col)*2);
            }
            #pragma unroll
            for (int nb = 0; nb < NI/2; nb++){
                int nrow = wx*(8*NI) + nb*16 + r + (q >> 1)*8;
                int ncol = ks*16 + (q & 1)*8;
                ldsm4(bf2[nb], sB + cur*strB + (uint32_t)(nrow*PITCH + ncol)*2);
            }
            #pragma unroll
            for (int mi = 0; mi < MI; mi++)
                #pragma unroll
                for (int ni = 0; ni < NI; ni++)
                    mma_bf16(acc[mi][ni], af[mi], &bf2[ni>>1][(ni&1)*2]);
        }
        if (more){
            if (ABF == 0){
                if (MI == 1) *(uint2*)&As[nxt][arow][aq] = cvt4(pa[0]);
                else { *(uint4*)&As[nxt][arow][aq] = cvt8(pa[0], pa[1]);
                       if (MI == 4) *(uint4*)&As[nxt][arow][aq+8] = cvt8(pa[2], pa[3]); }
            }
            CPA_WAIT0;
            __syncthreads();
        }
    }

    float* Cf = (float*)Cv + blockIdx.z * sCz;
    __nv_bfloat16* Ch = (__nv_bfloat16*)Cv + blockIdx.z * sCz;
    #pragma unroll
    for (int mi = 0; mi < MI; mi++){
        #pragma unroll
        for (int ni = 0; ni < NI; ni++){
            int row = m0 + wy*(MI*16) + mi*16 + (lane >> 2);
            int col = n0 + wx*(8*NI) + ni*8 + (lane & 3)*2;
            #pragma unroll
            for (int h = 0; h < 2; h++){
                float2 v = make_float2(acc[mi][ni][2*h], acc[mi][ni][2*h+1]);
                size_t off = (size_t)(row + h*8)*ldc + col;
                if (EPI == 1){
                    v.x = softplus_f(v.x + bias[col]);
                    v.y = softplus_f(v.y + bias[col+1]);
                } else if (EPI == 2){
                    float2 o = *(const float2*)(Cf + off);
                    v.x += o.x; v.y += o.y;
                } else if (EPI == 3){
                    v.x = fmaxf(v.x + bias[col], 0.f);
                    v.y = fmaxf(v.y + bias[col+1], 0.f);
                } else if (EPI == 4){
                    v.x = shrink_f(v.x + bias[col]);
                    v.y = shrink_f(v.y + bias[col+1]);
                }
                if (CBF) *(__nv_bfloat162*)(Ch + off) = __floats2bfloat162_rn(v.x, v.y);
                else     *(float2*)(Cf + off) = v;
            }
        }
    }
}

// ---------------- fused weight conversion ----------------
#define WN_IE  (2048*512)
#define WN_OE  (512*1024)
#define WN_DE  (1024*32)
#define WN_W1  (4*256*256)
#define WN_W2  (4*256*256)
#define WN_XP  (256*1024)
#define WN_TOT (WN_IE+WN_OE+WN_DE+WN_W1+WN_W2+WN_XP)
__global__ void k_wext_all(const float* __restrict__ in_proj_w,
                           const float* __restrict__ out_proj_w,
                           const float* __restrict__ dt_proj_w,
                           const float* __restrict__ x_proj_w){
    int idx = blockIdx.x * blockDim.x + threadIdx.x;
    if (idx >= WN_TOT) return;
    float x; __nv_bfloat16* dst; int local;
    if (idx < WN_IE){ local = idx; x = in_proj_w[local]; dst = g_wie; }
    else if (idx < WN_IE+WN_OE){ local = idx - WN_IE; x = out_proj_w[local]; dst = g_woe; }
    else if (idx < WN_IE+WN_OE+WN_DE){ local = idx - WN_IE-WN_OE; x = dt_proj_w[local]; dst = g_wde; }
    else if (idx < WN_IE+WN_OE+WN_DE+WN_W1){ local = idx - WN_IE-WN_OE-WN_DE; x = g_W1[local]; dst = g_w1e; }
    else if (idx < WN_IE+WN_OE+WN_DE+WN_W1+WN_W2){ local = idx - WN_IE-WN_OE-WN_DE-WN_W1; x = g_W2[local]; dst = g_w2e; }
    else {
        local = idx - WN_IE-WN_OE-WN_DE-WN_W1-WN_W2;
        int n = local >> 10, k = local & 1023;
        x = (n < 160) ? x_proj_w[n*1024 + k] : 0.f;
        dst = g_xpe;
    }
    dst[local] = __float2bfloat16_rn(x);
}

// ---------------- layernorm -> bf16 ----------------
__global__ void k_layernorm(const float* __restrict__ x, const float* __restrict__ w,
                            const float* __restrict__ b, __nv_bfloat16* __restrict__ out){
    int row = blockIdx.x;
    const float* xr = x + (size_t)row * DIM;
    int tid = threadIdx.x;
    float v0 = xr[tid], v1 = xr[tid + 256];
    float s = v0 + v1, q = v0*v0 + v1*v1;
    __shared__ float ss[8], sq[8];
    for (int o = 16; o; o >>= 1){ s += __shfl_down_sync(~0u, s, o); q += __shfl_down_sync(~0u, q, o); }
    if ((tid & 31) == 0){ ss[tid >> 5] = s; sq[tid >> 5] = q; }
    __syncthreads();
    __shared__ float mean_s, rstd_s;
    if (tid == 0){
        float S = 0.f, Q = 0.f;
        #pragma unroll
        for (int i = 0; i < 8; i++){ S += ss[i]; Q += sq[i]; }
        float m = S * (1.f/DIM);
        float var = Q * (1.f/DIM) - m*m;
        mean_s = m; rstd_s = rsqrtf(var + 1e-5f);
    }
    __syncthreads();
    float m = mean_s, rr = rstd_s;
    out[(size_t)row*DIM + tid]       = __float2bfloat16_rn((v0 - m)*rr*w[tid]       + b[tid]);
    out[(size_t)row*DIM + tid + 256] = __float2bfloat16_rn((v1 - m)*rr*w[tid + 256] + b[tid + 256]);
}

// ---------------- fused layernorm + forward DFT-4 ----------------
__global__ void k_layernorm_fft(const float* __restrict__ x, const float* __restrict__ w,
                                const float* __restrict__ b){
    int row = blockIdx.x;
    const float* xr = x + (size_t)row * DIM;
    int tid = threadIdx.x;
    __shared__ float sx[DIM];
    float v0 = xr[tid], v1 = xr[tid + 256];
    float s = v0 + v1, q = v0*v0 + v1*v1;
    __shared__ float ss[8], sq[8];
    for (int o = 16; o; o >>= 1){ s += __shfl_down_sync(~0u, s, o); q += __shfl_down_sync(~0u, q, o); }
    if ((tid & 31) == 0){ ss[tid >> 5] = s; sq[tid >> 5] = q; }
    __syncthreads();
    __shared__ float mean_s, rstd_s;
    if (tid == 0){
        float S = 0.f, Q = 0.f;
        #pragma unroll
        for (int i = 0; i < 8; i++){ S += ss[i]; Q += sq[i]; }
        float m = S * (1.f/DIM);
        float var = Q * (1.f/DIM) - m*m;
        mean_s = m; rstd_s = rsqrtf(var + 1e-5f);
    }
    __syncthreads();
    float m = mean_s, rr = rstd_s;
    sx[tid]       = (v0 - m)*rr*w[tid]       + b[tid];
    sx[tid + 256] = (v1 - m)*rr*w[tid + 256] + b[tid + 256];
    __syncthreads();
    if (tid < 128){
        int j = tid;
        float x0 = sx[j], x1 = sx[j+128], x2 = sx[j+256], x3 = sx[j+384];
        float* qq = g_fr + (size_t)row * 1024 + j;
        qq[0]   = x0 + x1 + x2 + x3;  qq[128] = 0.f;
        qq[256] = x0 - x2;            qq[384] = -(x1 - x3);
        qq[512] = x0 - x1 + x2 - x3;  qq[640] = 0.f;
        qq[768] = x0 - x2;            qq[896] = x1 - x3;
    }
}

// ---------------- causal depthwise conv + silu -> bf16 ----------------
__global__ void k_conv_silu(const float* __restrict__ conv_w, const float* __restrict__ conv_b){
    int idx = blockIdx.x * blockDim.x + threadIdx.x;
    if (idx >= ROWS * DI) return;
    int c = idx & (DI - 1);
    int l = (idx >> 10) & (LSEQ - 1);
    int b = idx >> 20;
    const float* xm = g_xz + (size_t)b * LSEQ * (2*DI);
    float acc = conv_b[c];
    #pragma unroll
    for (int k = 0; k < DC; k++){
        int lp = l + k - (DC - 1);
        if (lp >= 0) acc = fmaf(conv_w[c*DC + k], xm[(size_t)lp*(2*DI) + c], acc);
    }
    g_xmch[idx] = __float2bfloat16_rn(silu_f(acc));
}

// ---------------- selective scan + fused gate ----------------
#define SC_LT 16
__global__ void __launch_bounds__(256) k_scan2(const float* __restrict__ A_log,
                                               const float* __restrict__ Dv){
    __shared__ float sdt[SC_LT][8], su[SC_LT][8];
    __shared__ float sB[SC_LT][64], sC[SC_LT][64];
    __shared__ float sy[SC_LT][8];
    const int tid = threadIdx.x, w = tid >> 5, lane = tid & 31;
    const int b = blockIdx.x >> 7;
    const int dblk = blockIdx.x & 127;
    const int d0 = dblk * 8;
    const int d = d0 + w;
    const float A0 = -__expf(A_log[d*DS + lane]);
    const float A1 = -__expf(A_log[d*DS + 32 + lane]);
    const float* pdt = g_dt + (size_t)b*LSEQ*DI;
    const __nv_bfloat16* puh = g_xmch + (size_t)b*LSEQ*DI;
    const float* pp  = g_proj + (size_t)b*LSEQ*256;
    const float* pz  = g_xz   + (size_t)b*LSEQ*(2*DI) + DI;
    __nv_bfloat16* py = g_yh  + (size_t)b*LSEQ*DI;
    float h0 = 0.f, h1 = 0.f;
    for (int l0 = 0; l0 < LSEQ; l0 += SC_LT){
        if (tid < SC_LT*8){
            int s = tid >> 3, j = tid & 7;
            sdt[s][j] = pdt[(size_t)(l0+s)*DI + d0 + j];
            su [s][j] = __bfloat162float(puh[(size_t)(l0+s)*DI + d0 + j]);
        }
        {
            int s = tid >> 4, j4 = tid & 15;
            const float* pr = pp + (size_t)(l0+s)*256;
            *(float4*)&sB[s][j4*4] = *(const float4*)(pr + 32 + j4*4);
            *(float4*)&sC[s][j4*4] = *(const float4*)(pr + 96 + j4*4);
        }
        __syncthreads();
        float dA0[SC_LT], dA1[SC_LT], du[SC_LT];
        #pragma unroll
        for (int s = 0; s < SC_LT; s++){
            float dtv = sdt[s][w];
            dA0[s] = __expf(dtv*A0);
            dA1[s] = __expf(dtv*A1);
            du[s]  = dtv * su[s][w];
        }
        #pragma unroll
        for (int half = 0; half < 2; half++){
            float hs0[8], hs1[8];
            #pragma unroll
            for (int t = 0; t < 8; t++){
                int s = half*8 + t;
                h0 = fmaf(dA0[s], h0, du[s]*sB[s][lane]);
                h1 = fmaf(dA1[s], h1, du[s]*sB[s][lane+32]);
                hs0[t] = h0; hs1[t] = h1;
            }
            #pragma unroll
            for (int t = 0; t < 8; t++){
                int s = half*8 + t;
                float yv = hs0[t]*sC[s][lane] + hs1[t]*sC[s][lane+32];
                #pragma unroll
                for (int o = 16; o; o >>= 1) yv += __shfl_down_sync(~0u, yv, o);
                if (lane == 0) sy[s][w] = yv;
            }
        }
        __syncthreads();
        if (tid < SC_LT*8){
            int s = tid >> 3, j = tid & 7;
            size_t off = (size_t)(l0+s)*DI + d0 + j;
            float z = pz[(size_t)(l0+s)*(2*DI) + d0 + j];
            float y = fmaf(su[s][j], Dv[d0+j], sy[s][j]);
            py[off] = __float2bfloat16_rn(y * silu_f(z));
        }
        __syncthreads();
    }
}

// ---------------- build EinFFT real-GEMM weights/biases ----------------
__global__ void k_build(const float* __restrict__ cw1, const float* __restrict__ cw2,
                        const float* __restrict__ cb1, const float* __restrict__ cb2){
    int idx = blockIdx.x * blockDim.x + threadIdx.x;
    if (idx >= 4*256*256) return;
    int k = idx & 255, n = (idx >> 8) & 255, b = idx >> 16;
    int j = n & 127, d = k & 127;
    bool nre = n < 128, kre = k < 128;
    float w0a = cw1[b*16384 + d*128 + j];
    float w1a = cw1[65536 + b*16384 + d*128 + j];
    g_W1[idx] = nre ? (kre ? w0a : -w1a) : (kre ? w1a : w0a);
    float w0b = cw2[b*16384 + d*128 + j];
    float w1b = cw2[65536 + b*16384 + d*128 + j];
    g_W2[idx] = nre ? (kre ? w0b : -w1b) : (kre ? w1b : w0b);
    if (k == 0){
        g_b1[b*256 + n] = nre ? cb1[b*128 + j] : cb1[512 + b*128 + j];
        g_b2[b*256 + n] = nre ? cb2[b*128 + j] : cb2[512 + b*128 + j];
    }
}

// ---------------- 1024-pt radix-4 FFT along N, 4 columns/block (256 CTAs) ----------------
__global__ void k_fft1024r4(float sign){
    extern __shared__ float2 shm[];
    float2* tw = shm;
    float2* sh = shm + 1024;
    const int tid = threadIdx.x; // 512
    int blk = blockIdx.x;
    int b = blk >> 7;
    int rem = blk & 127;
    int kblk = rem >> 5, j4 = rem & 31;
    float* base = g_fr + (size_t)b * 1024 * 1024 + kblk*256 + j4*4;

    #pragma unroll
    for (int r = 0; r < 2; r++){
        int i = tid + r*512;
        float s, cc;
        sincosf(sign * 6.283185307179586f * (float)i / 1024.f, &s, &cc);
        tw[i] = make_float2(cc, s);
    }

    #pragma unroll
    for (int r = 0; r < 2; r++){
        int n = tid + r*512;
        int rv = ((n & 3) << 8) | (((n >> 2) & 3) << 6) | (((n >> 4) & 3) << 4)
               | (((n >> 6) & 3) << 2) | ((n >> 8) & 3);
        float4 re = *(const float4*)(base + (size_t)n*1024);
        float4 im = *(const float4*)(base + (size_t)n*1024 + 128);
        sh[0*1025 + rv] = make_float2(re.x, im.x);
        sh[1*1025 + rv] = make_float2(re.y, im.y);
        sh[2*1025 + rv] = make_float2(re.z, im.z);
        sh[3*1025 + rv] = make_float2(re.w, im.w);
    }
    __syncthreads();

    const int c = tid & 3, bf0 = tid >> 2;
    float2* S = sh + c*1025;
    #pragma unroll
    for (int st = 0; st < 5; st++){
        const int q = 1 << (2*st);
        const int tsh = 8 - 2*st;
        #pragma unroll
        for (int r = 0; r < 2; r++){
            int bf = bf0 + r*128;
            int j = bf & (q - 1);
            int i1 = ((bf & ~(q - 1)) << 2) | j;
            float2 x0 = S[i1], x1 = S[i1+q], x2 = S[i1+2*q], x3 = S[i1+3*q];
            if (st > 0){
                int j1 = j << tsh;
                x1 = cmulf(x1, tw[j1]);
                x2 = cmulf(x2, tw[2*j1]);
                x3 = cmulf(x3, tw[3*j1]);
            }
            float2 t0 = cadd(x0, x2), t1 = csub(x0, x2);
            float2 t2 = cadd(x1, x3), t3 = csub(x1, x3);
            float2 t3r = make_float2(-sign*t3.y, sign*t3.x);
            S[i1]       = cadd(t0, t2);
            S[i1+q]     = cadd(t1, t3r);
            S[i1+2*q]   = csub(t0, t2);
            S[i1+3*q]   = csub(t1, t3r);
        }
        __syncthreads();
    }

    const float sc = 0.015625f;
    #pragma unroll
    for (int r = 0; r < 2; r++){
        int n = tid + r*512;
        float2 v0 = sh[0*1025 + n], v1 = sh[1*1025 + n];
        float2 v2 = sh[2*1025 + n], v3 = sh[3*1025 + n];
        *(float4*)(base + (size_t)n*1024)       = make_float4(v0.x*sc, v1.x*sc, v2.x*sc, v3.x*sc);
        *(float4*)(base + (size_t)n*1024 + 128) = make_float4(v0.y*sc, v1.y*sc, v2.y*sc, v3.y*sc);
    }
}
#define FFT_SMEM ((1024 + 4*1025) * 8)

// ---------------- inverse 4-point DFT along NB, real part, add into out ----------------
__global__ void k_fft4_inv_add(float* __restrict__ out){
    int idx = blockIdx.x * blockDim.x + threadIdx.x;
    if (idx >= ROWS * 128) return;
    int j = idx & 127, row = idx >> 7;
    const float* q = g_fr + (size_t)row * 1024 + j;
    float r0 = q[0];
    float r1 = q[256], i1 = q[384];
    float r2 = q[512];
    float r3 = q[768], i3 = q[896];
    float* o = out + (size_t)row * DIM + j;
    o[0]   += r0 + r1 + r2 + r3;
    o[128] += r0 - i1 - r2 + i3;
    o[256] += r0 - r1 + r2 - r3;
    o[384] += r0 + i1 - r2 - i3;
}

// ---------------- host launch ----------------
extern "C" void kernel_launch(void* const* d_in, const int* in_sizes, int n_in,
                              void* d_out, int out_size){
    const float* x_in      = (const float*)d_in[0];
    const float* ln_w      = (const float*)d_in[1];
    const float* ln_b      = (const float*)d_in[2];
    const float* in_proj_w = (const float*)d_in[3];
    const float* conv_w    = (const float*)d_in[4];
    const float* conv_b    = (const float*)d_in[5];
    const float* x_proj_w  = (const float*)d_in[6];
    const float* dt_proj_w = (const float*)d_in[7];
    const float* dt_proj_b = (const float*)d_in[8];
    const float* A_log     = (const float*)d_in[9];
    const float* Dv        = (const float*)d_in[10];
    const float* out_proj_w= (const float*)d_in[11];
    const float* norm2_w   = (const float*)d_in[12];
    const float* norm2_b   = (const float*)d_in[13];
    const float* cw1       = (const float*)d_in[14];
    const float* cw2       = (const float*)d_in[15];
    const float* cb1       = (const float*)d_in[16];
    const float* cb2       = (const float*)d_in[17];
    float* xout = (float*)d_out;

    float *p_xz, *p_proj, *p_dt, *p_fr, *p_b1, *p_b2;
    __nv_bfloat16 *p_lnh, *p_xmch, *p_yh, *p_r1h, *p_wie, *p_woe, *p_wde, *p_w1e, *p_w2e, *p_xpe;
    cudaGetSymbolAddress((void**)&p_xz,    g_xz);
    cudaGetSymbolAddress((void**)&p_proj,  g_proj);
    cudaGetSymbolAddress((void**)&p_dt,    g_dt);
    cudaGetSymbolAddress((void**)&p_fr,    g_fr);
    cudaGetSymbolAddress((void**)&p_b1,    g_b1);
    cudaGetSymbolAddress((void**)&p_b2,    g_b2);
    cudaGetSymbolAddress((void**)&p_lnh,   g_lnh);
    cudaGetSymbolAddress((void**)&p_xmch,  g_xmch);
    cudaGetSymbolAddress((void**)&p_yh,    g_yh);
    cudaGetSymbolAddress((void**)&p_r1h,   g_r1h);
    cudaGetSymbolAddress((void**)&p_wie,   g_wie);
    cudaGetSymbolAddress((void**)&p_woe,   g_woe);
    cudaGetSymbolAddress((void**)&p_wde,   g_wde);
    cudaGetSymbolAddress((void**)&p_w1e,   g_w1e);
    cudaGetSymbolAddress((void**)&p_w2e,   g_w2e);
    cudaGetSymbolAddress((void**)&p_xpe,   g_xpe);

    cudaFuncSetAttribute(k_fft1024r4, cudaFuncAttributeMaxDynamicSharedMemorySize, FFT_SMEM);

    cudaMemcpyAsync(xout, x_in, (size_t)ROWS*DIM*sizeof(float), cudaMemcpyDeviceToDevice, 0);

    k_build<<<(4*256*256 + 255)/256, 256>>>(cw1, cw2, cb1, cb2);
    k_wext_all<<<(WN_TOT + 255)/256, 256>>>(in_proj_w, out_proj_w, dt_proj_w, x_proj_w);

    for (int blk = 0; blk < 2; blk++){
        // ---- Mamba ----
        k_layernorm<<<ROWS, 256>>>(xout, ln_w, ln_b, p_lnh);
        k_hgemm<0,4,4,1,0><<<dim3(16,16,1), 256>>>(512,
            p_lnh, DIM, 0, p_wie, 512, 0, p_xz, 2*DI, 0, nullptr, 0);
        k_conv_silu<<<(ROWS*DI + 255)/256, 256>>>(conv_w, conv_b);
        k_hgemm<0,1,2,1,0><<<dim3(4,64,1), 256>>>(1024,
            p_xmch, DI, 0, p_xpe, 1024, 0, p_proj, 256, 0, nullptr, 0);
        k_hgemm<1,2,4,0,0><<<dim3(8,32,1), 256>>>(32,
            p_proj, 256, 0, p_wde, 32, 0, p_dt, DI, 0, dt_proj_b, 0);
        k_scan2<<<256, 256>>>(A_log, Dv);
        k_hgemm<2,2,2,1,0><<<dim3(8,32,1), 256>>>(1024,
            p_yh, DI, 0, p_woe, 1024, 0, xout, DIM, 0, nullptr, 0);

        // ---- EinFFT ----
        k_layernorm_fft<<<ROWS, 256>>>(xout, norm2_w, norm2_b);
        k_fft1024r4<<<256, 512, FFT_SMEM>>>(-1.f);
        k_hgemm<3,2,2,0,1><<<dim3(4,32,4), 256>>>(256,
            p_fr, 1024, 256, p_w1e, 256, 256*256, p_r1h, 1024, 256, p_b1, 256);
        k_hgemm<4,2,2,1,0><<<dim3(4,32,4), 256>>>(256,
            p_r1h, 1024, 256, p_w2e, 256, 256*256, p_fr, 1024, 256, p_b2, 256);
        k_fft1024r4<<<256, 512, FFT_SMEM>>>(1.f);
        k_fft4_inv_add<<<(ROWS*128 + 255)/256, 256>>>(xout);
    }
}

// round 17
// speedup vs baseline: 1.1819x; 1.0359x over previous
#include <cuda_runtime.h>
#include <cuda_bf16.h>
#include <math.h>
#include <stdint.h>

// ---------------- problem constants ----------------
#define BSZ   2
#define LSEQ  1024
#define DIM   512
#define DI    1024
#define DS    64
#define DTR   32
#define DC    4
#define ROWS  (BSZ*LSEQ)    // 2048
#define LAMB  0.01f

typedef unsigned long long u64;

// ---------------- scratch ----------------
__device__ float  g_xz  [ROWS*2*DI];
__device__ float  g_proj[ROWS*256];
__device__ float  g_dt  [ROWS*DI];
__device__ float  g_fr  [ROWS*1024];
__device__ float  g_W1  [4*256*256];
__device__ float  g_W2  [4*256*256];
__device__ float  g_b1  [4*256];
__device__ float  g_b2  [4*256];
// bf16 activations
__device__ __nv_bfloat16 g_lnh [ROWS*DIM];
__device__ __nv_bfloat16 g_xmch[ROWS*DI];
__device__ __nv_bfloat16 g_yh  [ROWS*DI];
__device__ __nv_bfloat16 g_r1h [ROWS*1024];
// bf16 weights
__device__ __nv_bfloat16 g_wie[2048*512];
__device__ __nv_bfloat16 g_woe[512*1024];
__device__ __nv_bfloat16 g_wde[1024*32];
__device__ __nv_bfloat16 g_w1e[4*256*256];
__device__ __nv_bfloat16 g_w2e[4*256*256];
__device__ __nv_bfloat16 g_xpe[256*1024];

__device__ __forceinline__ float silu_f(float x){ return x / (1.f + expf(-x)); }
__device__ __forceinline__ float softplus_f(float x){ return x > 20.f ? x : log1pf(expf(x)); }
__device__ __forceinline__ float shrink_f(float x){
    return x > LAMB ? x - LAMB : (x < -LAMB ? x + LAMB : 0.f);
}

// ---------------- complex helpers ----------------
__device__ __forceinline__ float2 cadd(float2 a, float2 b){ return make_float2(a.x+b.x, a.y+b.y); }
__device__ __forceinline__ float2 csub(float2 a, float2 b){ return make_float2(a.x-b.x, a.y-b.y); }
__device__ __forceinline__ float2 cmulf(float2 a, float2 b){
    return make_float2(a.x*b.x - a.y*b.y, a.x*b.y + a.y*b.x);
}

// ---------------- mma / async helpers ----------------
__device__ __forceinline__ uint32_t s2u(const void* p){
    uint32_t a;
    asm("{ .reg .u64 t; cvta.to.shared.u64 t, %1; cvt.u32.u64 %0, t; }" : "=r"(a) : "l"(p));
    return a;
}
__device__ __forceinline__ void ldsm4(uint32_t* r, uint32_t addr){
    asm volatile("ldmatrix.sync.aligned.m8n8.x4.shared.b16 {%0,%1,%2,%3}, [%4];"
        : "=r"(r[0]), "=r"(r[1]), "=r"(r[2]), "=r"(r[3]) : "r"(addr));
}
__device__ __forceinline__ void mma_bf16(float* c, const uint32_t* a, const uint32_t* b){
    asm volatile("mma.sync.aligned.m16n8k16.row.col.f32.bf16.bf16.f32 "
        "{%0,%1,%2,%3}, {%4,%5,%6,%7}, {%8,%9}, {%0,%1,%2,%3};"
        : "+f"(c[0]), "+f"(c[1]), "+f"(c[2]), "+f"(c[3])
        : "r"(a[0]), "r"(a[1]), "r"(a[2]), "r"(a[3]), "r"(b[0]), "r"(b[1]));
}
__device__ __forceinline__ void cpa16(uint32_t dst, const void* src){
    asm volatile("cp.async.cg.shared.global [%0], [%1], 16;" :: "r"(dst), "l"(src));
}
#define CPA_COMMIT asm volatile("cp.async.commit_group;" ::: "memory")
#define CPA_WAIT0  asm volatile("cp.async.wait_group 0;" ::: "memory")

__device__ __forceinline__ uint4 cvt8(float4 v0, float4 v1){
    union { uint4 u; __nv_bfloat162 h[4]; } r;
    r.h[0] = __floats2bfloat162_rn(v0.x, v0.y);
    r.h[1] = __floats2bfloat162_rn(v0.z, v0.w);
    r.h[2] = __floats2bfloat162_rn(v1.x, v1.y);
    r.h[3] = __floats2bfloat162_rn(v1.z, v1.w);
    return r.u;
}
__device__ __forceinline__ uint2 cvt4(float4 v0){
    union { uint2 u; __nv_bfloat162 h[2]; } r;
    r.h[0] = __floats2bfloat162_rn(v0.x, v0.y);
    r.h[1] = __floats2bfloat162_rn(v0.z, v0.w);
    return r.u;
}

// ---------------- tensor-core bf16 GEMM with cp.async pipeline ----------------
// C[M,N] = A[M,K] @ B[N,K]^T ; BM=32*MI, BN=32*NI, stage = KI*32 K (KI=2 requires ABF=1),
// 256 thr (8 warps 2x4), double-buffered smem.
// EPI: 0 store, 1 softplus(+bias), 2 +=, 3 relu(+bias), 4 softshrink(+bias)
template<int EPI, int MI, int NI, int ABF, int CBF, int KI>
__global__ void __launch_bounds__(256,2)
k_hgemm(int K,
        const void* __restrict__ Av, int lda, long long sAz,
        const __nv_bfloat16* __restrict__ Bw, int ldb, long long sBz,
        void* __restrict__ Cv, int ldc, long long sCz,
        const float* __restrict__ bias, long long sbz)
{
    constexpr int BM = 32*MI, BN = 32*NI;
    constexpr int PITCH = KI*32 + 8;
    __shared__ __align__(16) __nv_bfloat16 As[2][BM][PITCH];
    __shared__ __align__(16) __nv_bfloat16 Bs[2][BN][PITCH];
    const int tid = threadIdx.x, lane = tid & 31, wid = tid >> 5;
    const int wy = wid >> 2, wx = wid & 3;
    const int m0 = blockIdx.y * BM, n0 = blockIdx.x * BN;
    const float* Af = (const float*)Av + blockIdx.z * sAz;
    const __nv_bfloat16* Ah = (const __nv_bfloat16*)Av + blockIdx.z * sAz;
    Bw += blockIdx.z * sBz;
    if (EPI == 1 || EPI == 3 || EPI == 4) bias += blockIdx.z * sbz;

    float acc[MI][NI][4] = {};
    const uint32_t sA = s2u(&As[0][0][0]), sB = s2u(&Bs[0][0][0]);
    const uint32_t strA = BM*PITCH*2, strB = BN*PITCH*2;

    const int arow = (MI == 4) ? (tid >> 1) : (MI == 2 ? (tid >> 2) : (tid >> 3));
    const int aq   = (MI == 4) ? ((tid & 1) * 16) : (MI == 2 ? ((tid & 3) * 8) : ((tid & 7) * 4));
    const int nst = K / (KI*32);

    auto stageB = [&](int buf, int k0){
        #pragma unroll
        for (int l = 0; l < (BN*4*KI + 255)/256; l++){
            int e = tid + l*256;
            if (BN*4*KI < 256 && e >= BN*4*KI) break;
            int row = e / (4*KI), qo = (e % (4*KI)) * 8;
            cpa16(sB + buf*strB + (uint32_t)(row*PITCH + qo)*2,
                  Bw + (size_t)(n0+row)*ldb + k0 + qo);
        }
    };
    auto stageAh = [&](int buf, int k0){
        #pragma unroll
        for (int l = 0; l < (BM*4*KI + 255)/256; l++){
            int e = tid + l*256;
            if (BM*4*KI < 256 && e >= BM*4*KI) break;
            int row = e / (4*KI), qo = (e % (4*KI)) * 8;
            cpa16(sA + buf*strA + (uint32_t)(row*PITCH + qo)*2,
                  Ah + (size_t)(m0+row)*lda + k0 + qo);
        }
    };

    stageB(0, 0);
    if (ABF == 1){
        stageAh(0, 0);
    } else {
        float4 pa[MI];
        const float* ap = Af + (size_t)(m0+arow)*lda + aq;
        #pragma unroll
        for (int i = 0; i < MI; i++) pa[i] = *(const float4*)(ap + 4*i);
        if (MI == 1) *(uint2*)&As[0][arow][aq] = cvt4(pa[0]);
        else { *(uint4*)&As[0][arow][aq] = cvt8(pa[0], pa[1]);
               if (MI == 4) *(uint4*)&As[0][arow][aq+8] = cvt8(pa[2], pa[3]); }
    }
    CPA_COMMIT;
    CPA_WAIT0;
    __syncthreads();

    const int q = lane >> 3, r = lane & 7;

    for (int ch = 0; ch < nst; ch++){
        const int cur = ch & 1, nxt = cur ^ 1;
        float4 pa[MI];
        const bool more = (ch + 1 < nst);
        if (more){
            int k0 = (ch+1) * KI*32;
            stageB(nxt, k0);
            if (ABF == 1) stageAh(nxt, k0);
            else {
                const float* ap = Af + (size_t)(m0+arow)*lda + k0 + aq;
                #pragma unroll
                for (int i = 0; i < MI; i++) pa[i] = *(const float4*)(ap + 4*i);
            }
            CPA_COMMIT;
        }
        #pragma unroll
        for (int ks = 0; ks < 2*KI; ks++){
            uint32_t af[MI][4], bf2[NI/2][4];
            #pragma unroll
            for (int mi = 0; mi < MI; mi++){
                int row = wy*(MI*16) + mi*16 + r + (q & 1)*8;
                int col = ks*16 + (q >> 1)*8;
                ldsm4(af[mi], sA + cur*strA + (uint32_t)(row*PITCH + col)*2);
            }
            #pragma unroll
            for (int nb = 0; nb < NI/2; nb++){
                int nrow = wx*(8*NI) + nb*16 + r + (q >> 1)*8;
                int ncol = ks*16 + (q & 1)*8;
                ldsm4(bf2[nb], sB + cur*strB + (uint32_t)(nrow*PITCH + ncol)*2);
            }
            #pragma unroll
            for (int mi = 0; mi < MI; mi++)
                #pragma unroll
                for (int ni = 0; ni < NI; ni++)
                    mma_bf16(acc[mi][ni], af[mi], &bf2[ni>>1][(ni&1)*2]);
        }
        if (more){
            if (ABF == 0){
                if (MI == 1) *(uint2*)&As[nxt][arow][aq] = cvt4(pa[0]);
                else { *(uint4*)&As[nxt][arow][aq] = cvt8(pa[0], pa[1]);
                       if (MI == 4) *(uint4*)&As[nxt][arow][aq+8] = cvt8(pa[2], pa[3]); }
            }
            CPA_WAIT0;
            __syncthreads();
        }
    }

    float* Cf = (float*)Cv + blockIdx.z * sCz;
    __nv_bfloat16* Ch = (__nv_bfloat16*)Cv + blockIdx.z * sCz;
    #pragma unroll
    for (int mi = 0; mi < MI; mi++){
        #pragma unroll
        for (int ni = 0; ni < NI; ni++){
            int row = m0 + wy*(MI*16) + mi*16 + (lane >> 2);
            int col = n0 + wx*(8*NI) + ni*8 + (lane & 3)*2;
            #pragma unroll
            for (int h = 0; h < 2; h++){
                float2 v = make_float2(acc[mi][ni][2*h], acc[mi][ni][2*h+1]);
                size_t off = (size_t)(row + h*8)*ldc + col;
                if (EPI == 1){
                    v.x = softplus_f(v.x + bias[col]);
                    v.y = softplus_f(v.y + bias[col+1]);
                } else if (EPI == 2){
                    float2 o = *(const float2*)(Cf + off);
                    v.x += o.x; v.y += o.y;
                } else if (EPI == 3){
                    v.x = fmaxf(v.x + bias[col], 0.f);
                    v.y = fmaxf(v.y + bias[col+1], 0.f);
                } else if (EPI == 4){
                    v.x = shrink_f(v.x + bias[col]);
                    v.y = shrink_f(v.y + bias[col+1]);
                }
                if (CBF) *(__nv_bfloat162*)(Ch + off) = __floats2bfloat162_rn(v.x, v.y);
                else     *(float2*)(Cf + off) = v;
            }
        }
    }
}

// ---------------- fused weight conversion ----------------
#define WN_IE  (2048*512)
#define WN_OE  (512*1024)
#define WN_DE  (1024*32)
#define WN_W1  (4*256*256)
#define WN_W2  (4*256*256)
#define WN_XP  (256*1024)
#define WN_TOT (WN_IE+WN_OE+WN_DE+WN_W1+WN_W2+WN_XP)
__global__ void k_wext_all(const float* __restrict__ in_proj_w,
                           const float* __restrict__ out_proj_w,
                           const float* __restrict__ dt_proj_w,
                           const float* __restrict__ x_proj_w){
    int idx = blockIdx.x * blockDim.x + threadIdx.x;
    if (idx >= WN_TOT) return;
    float x; __nv_bfloat16* dst; int local;
    if (idx < WN_IE){ local = idx; x = in_proj_w[local]; dst = g_wie; }
    else if (idx < WN_IE+WN_OE){ local = idx - WN_IE; x = out_proj_w[local]; dst = g_woe; }
    else if (idx < WN_IE+WN_OE+WN_DE){ local = idx - WN_IE-WN_OE; x = dt_proj_w[local]; dst = g_wde; }
    else if (idx < WN_IE+WN_OE+WN_DE+WN_W1){ local = idx - WN_IE-WN_OE-WN_DE; x = g_W1[local]; dst = g_w1e; }
    else if (idx < WN_IE+WN_OE+WN_DE+WN_W1+WN_W2){ local = idx - WN_IE-WN_OE-WN_DE-WN_W1; x = g_W2[local]; dst = g_w2e; }
    else {
        local = idx - WN_IE-WN_OE-WN_DE-WN_W1-WN_W2;
        int n = local >> 10, k = local & 1023;
        x = (n < 160) ? x_proj_w[n*1024 + k] : 0.f;
        dst = g_xpe;
    }
    dst[local] = __float2bfloat16_rn(x);
}

// ---------------- layernorm -> bf16 ----------------
__global__ void k_layernorm(const float* __restrict__ x, const float* __restrict__ w,
                            const float* __restrict__ b, __nv_bfloat16* __restrict__ out){
    int row = blockIdx.x;
    const float* xr = x + (size_t)row * DIM;
    int tid = threadIdx.x;
    float v0 = xr[tid], v1 = xr[tid + 256];
    float s = v0 + v1, q = v0*v0 + v1*v1;
    __shared__ float ss[8], sq[8];
    for (int o = 16; o; o >>= 1){ s += __shfl_down_sync(~0u, s, o); q += __shfl_down_sync(~0u, q, o); }
    if ((tid & 31) == 0){ ss[tid >> 5] = s; sq[tid >> 5] = q; }
    __syncthreads();
    __shared__ float mean_s, rstd_s;
    if (tid == 0){
        float S = 0.f, Q = 0.f;
        #pragma unroll
        for (int i = 0; i < 8; i++){ S += ss[i]; Q += sq[i]; }
        float m = S * (1.f/DIM);
        float var = Q * (1.f/DIM) - m*m;
        mean_s = m; rstd_s = rsqrtf(var + 1e-5f);
    }
    __syncthreads();
    float m = mean_s, rr = rstd_s;
    out[(size_t)row*DIM + tid]       = __float2bfloat16_rn((v0 - m)*rr*w[tid]       + b[tid]);
    out[(size_t)row*DIM + tid + 256] = __float2bfloat16_rn((v1 - m)*rr*w[tid + 256] + b[tid + 256]);
}

// ---------------- fused layernorm + forward DFT-4 ----------------
__global__ void k_layernorm_fft(const float* __restrict__ x, const float* __restrict__ w,
                                const float* __restrict__ b){
    int row = blockIdx.x;
    const float* xr = x + (size_t)row * DIM;
    int tid = threadIdx.x;
    __shared__ float sx[DIM];
    float v0 = xr[tid], v1 = xr[tid + 256];
    float s = v0 + v1, q = v0*v0 + v1*v1;
    __shared__ float ss[8], sq[8];
    for (int o = 16; o; o >>= 1){ s += __shfl_down_sync(~0u, s, o); q += __shfl_down_sync(~0u, q, o); }
    if ((tid & 31) == 0){ ss[tid >> 5] = s; sq[tid >> 5] = q; }
    __syncthreads();
    __shared__ float mean_s, rstd_s;
    if (tid == 0){
        float S = 0.f, Q = 0.f;
        #pragma unroll
        for (int i = 0; i < 8; i++){ S += ss[i]; Q += sq[i]; }
        float m = S * (1.f/DIM);
        float var = Q * (1.f/DIM) - m*m;
        mean_s = m; rstd_s = rsqrtf(var + 1e-5f);
    }
    __syncthreads();
    float m = mean_s, rr = rstd_s;
    sx[tid]       = (v0 - m)*rr*w[tid]       + b[tid];
    sx[tid + 256] = (v1 - m)*rr*w[tid + 256] + b[tid + 256];
    __syncthreads();
    if (tid < 128){
        int j = tid;
        float x0 = sx[j], x1 = sx[j+128], x2 = sx[j+256], x3 = sx[j+384];
        float* qq = g_fr + (size_t)row * 1024 + j;
        qq[0]   = x0 + x1 + x2 + x3;  qq[128] = 0.f;
        qq[256] = x0 - x2;            qq[384] = -(x1 - x3);
        qq[512] = x0 - x1 + x2 - x3;  qq[640] = 0.f;
        qq[768] = x0 - x2;            qq[896] = x1 - x3;
    }
}

// ---------------- causal depthwise conv + silu -> bf16 ----------------
__global__ void k_conv_silu(const float* __restrict__ conv_w, const float* __restrict__ conv_b){
    int idx = blockIdx.x * blockDim.x + threadIdx.x;
    if (idx >= ROWS * DI) return;
    int c = idx & (DI - 1);
    int l = (idx >> 10) & (LSEQ - 1);
    int b = idx >> 20;
    const float* xm = g_xz + (size_t)b * LSEQ * (2*DI);
    float acc = conv_b[c];
    #pragma unroll
    for (int k = 0; k < DC; k++){
        int lp = l + k - (DC - 1);
        if (lp >= 0) acc = fmaf(conv_w[c*DC + k], xm[(size_t)lp*(2*DI) + c], acc);
    }
    g_xmch[idx] = __float2bfloat16_rn(silu_f(acc));
}

// ---------------- selective scan + fused gate ----------------
#define SC_LT 16
__global__ void __launch_bounds__(256) k_scan2(const float* __restrict__ A_log,
                                               const float* __restrict__ Dv){
    __shared__ float sdt[SC_LT][8], su[SC_LT][8];
    __shared__ float sB[SC_LT][64], sC[SC_LT][64];
    __shared__ float sy[SC_LT][8];
    const int tid = threadIdx.x, w = tid >> 5, lane = tid & 31;
    const int b = blockIdx.x >> 7;
    const int dblk = blockIdx.x & 127;
    const int d0 = dblk * 8;
    const int d = d0 + w;
    const float A0 = -__expf(A_log[d*DS + lane]);
    const float A1 = -__expf(A_log[d*DS + 32 + lane]);
    const float* pdt = g_dt + (size_t)b*LSEQ*DI;
    const __nv_bfloat16* puh = g_xmch + (size_t)b*LSEQ*DI;
    const float* pp  = g_proj + (size_t)b*LSEQ*256;
    const float* pz  = g_xz   + (size_t)b*LSEQ*(2*DI) + DI;
    __nv_bfloat16* py = g_yh  + (size_t)b*LSEQ*DI;
    float h0 = 0.f, h1 = 0.f;
    for (int l0 = 0; l0 < LSEQ; l0 += SC_LT){
        if (tid < SC_LT*8){
            int s = tid >> 3, j = tid & 7;
            sdt[s][j] = pdt[(size_t)(l0+s)*DI + d0 + j];
            su [s][j] = __bfloat162float(puh[(size_t)(l0+s)*DI + d0 + j]);
        }
        {
            int s = tid >> 4, j4 = tid & 15;
            const float* pr = pp + (size_t)(l0+s)*256;
            *(float4*)&sB[s][j4*4] = *(const float4*)(pr + 32 + j4*4);
            *(float4*)&sC[s][j4*4] = *(const float4*)(pr + 96 + j4*4);
        }
        __syncthreads();
        float dA0[SC_LT], dA1[SC_LT], du[SC_LT];
        #pragma unroll
        for (int s = 0; s < SC_LT; s++){
            float dtv = sdt[s][w];
            dA0[s] = __expf(dtv*A0);
            dA1[s] = __expf(dtv*A1);
            du[s]  = dtv * su[s][w];
        }
        #pragma unroll
        for (int half = 0; half < 2; half++){
            float hs0[8], hs1[8];
            #pragma unroll
            for (int t = 0; t < 8; t++){
                int s = half*8 + t;
                h0 = fmaf(dA0[s], h0, du[s]*sB[s][lane]);
                h1 = fmaf(dA1[s], h1, du[s]*sB[s][lane+32]);
                hs0[t] = h0; hs1[t] = h1;
            }
            #pragma unroll
            for (int t = 0; t < 8; t++){
                int s = half*8 + t;
                float yv = hs0[t]*sC[s][lane] + hs1[t]*sC[s][lane+32];
                #pragma unroll
                for (int o = 16; o; o >>= 1) yv += __shfl_down_sync(~0u, yv, o);
                if (lane == 0) sy[s][w] = yv;
            }
        }
        __syncthreads();
        if (tid < SC_LT*8){
            int s = tid >> 3, j = tid & 7;
            size_t off = (size_t)(l0+s)*DI + d0 + j;
            float z = pz[(size_t)(l0+s)*(2*DI) + d0 + j];
            float y = fmaf(su[s][j], Dv[d0+j], sy[s][j]);
            py[off] = __float2bfloat16_rn(y * silu_f(z));
        }
        __syncthreads();
    }
}

// ---------------- build EinFFT real-GEMM weights/biases ----------------
__global__ void k_build(const float* __restrict__ cw1, const float* __restrict__ cw2,
                        const float* __restrict__ cb1, const float* __restrict__ cb2){
    int idx = blockIdx.x * blockDim.x + threadIdx.x;
    if (idx >= 4*256*256) return;
    int k = idx & 255, n = (idx >> 8) & 255, b = idx >> 16;
    int j = n & 127, d = k & 127;
    bool nre = n < 128, kre = k < 128;
    float w0a = cw1[b*16384 + d*128 + j];
    float w1a = cw1[65536 + b*16384 + d*128 + j];
    g_W1[idx] = nre ? (kre ? w0a : -w1a) : (kre ? w1a : w0a);
    float w0b = cw2[b*16384 + d*128 + j];
    float w1b = cw2[65536 + b*16384 + d*128 + j];
    g_W2[idx] = nre ? (kre ? w0b : -w1b) : (kre ? w1b : w0b);
    if (k == 0){
        g_b1[b*256 + n] = nre ? cb1[b*128 + j] : cb1[512 + b*128 + j];
        g_b2[b*256 + n] = nre ? cb2[b*128 + j] : cb2[512 + b*128 + j];
    }
}

// ---------------- 1024-pt radix-4 FFT along N, 4 columns/block (256 CTAs) ----------------
__global__ void k_fft1024r4(float sign){
    extern __shared__ float2 shm[];
    float2* tw = shm;
    float2* sh = shm + 1024;
    const int tid = threadIdx.x; // 512
    int blk = blockIdx.x;
    int b = blk >> 7;
    int rem = blk & 127;
    int kblk = rem >> 5, j4 = rem & 31;
    float* base = g_fr + (size_t)b * 1024 * 1024 + kblk*256 + j4*4;

    #pragma unroll
    for (int r = 0; r < 2; r++){
        int i = tid + r*512;
        float s, cc;
        sincosf(sign * 6.283185307179586f * (float)i / 1024.f, &s, &cc);
        tw[i] = make_float2(cc, s);
    }

    #pragma unroll
    for (int r = 0; r < 2; r++){
        int n = tid + r*512;
        int rv = ((n & 3) << 8) | (((n >> 2) & 3) << 6) | (((n >> 4) & 3) << 4)
               | (((n >> 6) & 3) << 2) | ((n >> 8) & 3);
        float4 re = *(const float4*)(base + (size_t)n*1024);
        float4 im = *(const float4*)(base + (size_t)n*1024 + 128);
        sh[0*1025 + rv] = make_float2(re.x, im.x);
        sh[1*1025 + rv] = make_float2(re.y, im.y);
        sh[2*1025 + rv] = make_float2(re.z, im.z);
        sh[3*1025 + rv] = make_float2(re.w, im.w);
    }
    __syncthreads();

    const int c = tid & 3, bf0 = tid >> 2;
    float2* S = sh + c*1025;
    #pragma unroll
    for (int st = 0; st < 5; st++){
        const int q = 1 << (2*st);
        const int tsh = 8 - 2*st;
        #pragma unroll
        for (int r = 0; r < 2; r++){
            int bf = bf0 + r*128;
            int j = bf & (q - 1);
            int i1 = ((bf & ~(q - 1)) << 2) | j;
            float2 x0 = S[i1], x1 = S[i1+q], x2 = S[i1+2*q], x3 = S[i1+3*q];
            if (st > 0){
                int j1 = j << tsh;
                x1 = cmulf(x1, tw[j1]);
                x2 = cmulf(x2, tw[2*j1]);
                x3 = cmulf(x3, tw[3*j1]);
            }
            float2 t0 = cadd(x0, x2), t1 = csub(x0, x2);
            float2 t2 = cadd(x1, x3), t3 = csub(x1, x3);
            float2 t3r = make_float2(-sign*t3.y, sign*t3.x);
            S[i1]       = cadd(t0, t2);
            S[i1+q]     = cadd(t1, t3r);
            S[i1+2*q]   = csub(t0, t2);
            S[i1+3*q]   = csub(t1, t3r);
        }
        __syncthreads();
    }

    const float sc = 0.015625f;
    #pragma unroll
    for (int r = 0; r < 2; r++){
        int n = tid + r*512;
        float2 v0 = sh[0*1025 + n], v1 = sh[1*1025 + n];
        float2 v2 = sh[2*1025 + n], v3 = sh[3*1025 + n];
        *(float4*)(base + (size_t)n*1024)       = make_float4(v0.x*sc, v1.x*sc, v2.x*sc, v3.x*sc);
        *(float4*)(base + (size_t)n*1024 + 128) = make_float4(v0.y*sc, v1.y*sc, v2.y*sc, v3.y*sc);
    }
}
#define FFT_SMEM ((1024 + 4*1025) * 8)

// ---------------- inverse DFT-4 + residual add + (optional) next-block layernorm ----------------
__global__ void k_fft4_inv_ln(float* __restrict__ out, int doLN,
                              const float* __restrict__ w, const float* __restrict__ b){
    int row = blockIdx.x;
    int j = threadIdx.x;        // 128
    __shared__ float sx[DIM];
    const float* qq = g_fr + (size_t)row * 1024 + j;
    float r0 = qq[0];
    float r1 = qq[256], i1 = qq[384];
    float r2 = qq[512];
    float r3 = qq[768], i3 = qq[896];
    float* o = out + (size_t)row * DIM + j;
    float v0 = o[0]   + (r0 + r1 + r2 + r3);
    float v1 = o[128] + (r0 - i1 - r2 + i3);
    float v2 = o[256] + (r0 - r1 + r2 - r3);
    float v3 = o[384] + (r0 + i1 - r2 - i3);
    o[0] = v0; o[128] = v1; o[256] = v2; o[384] = v3;
    if (!doLN) return;
    sx[j] = v0; sx[j+128] = v1; sx[j+256] = v2; sx[j+384] = v3;
    float s = v0+v1+v2+v3, q = v0*v0+v1*v1+v2*v2+v3*v3;
    __shared__ float ss[4], sq[4];
    for (int oo = 16; oo; oo >>= 1){ s += __shfl_down_sync(~0u, s, oo); q += __shfl_down_sync(~0u, q, oo); }
    if ((j & 31) == 0){ ss[j >> 5] = s; sq[j >> 5] = q; }
    __syncthreads();
    __shared__ float mean_s, rstd_s;
    if (j == 0){
        float S = ss[0]+ss[1]+ss[2]+ss[3], Q = sq[0]+sq[1]+sq[2]+sq[3];
        float m = S * (1.f/DIM);
        mean_s = m; rstd_s = rsqrtf(Q*(1.f/DIM) - m*m + 1e-5f);
    }
    __syncthreads();
    float m = mean_s, rr = rstd_s;
    __nv_bfloat16* dst = g_lnh + (size_t)row * DIM;
    #pragma unroll
    for (int t = 0; t < 4; t++){
        int idx = j + t*128;
        dst[idx] = __float2bfloat16_rn((sx[idx] - m)*rr*w[idx] + b[idx]);
    }
}

// ---------------- host launch ----------------
extern "C" void kernel_launch(void* const* d_in, const int* in_sizes, int n_in,
                              void* d_out, int out_size){
    const float* x_in      = (const float*)d_in[0];
    const float* ln_w      = (const float*)d_in[1];
    const float* ln_b      = (const float*)d_in[2];
    const float* in_proj_w = (const float*)d_in[3];
    const float* conv_w    = (const float*)d_in[4];
    const float* conv_b    = (const float*)d_in[5];
    const float* x_proj_w  = (const float*)d_in[6];
    const float* dt_proj_w = (const float*)d_in[7];
    const float* dt_proj_b = (const float*)d_in[8];
    const float* A_log     = (const float*)d_in[9];
    const float* Dv        = (const float*)d_in[10];
    const float* out_proj_w= (const float*)d_in[11];
    const float* norm2_w   = (const float*)d_in[12];
    const float* norm2_b   = (const float*)d_in[13];
    const float* cw1       = (const float*)d_in[14];
    const float* cw2       = (const float*)d_in[15];
    const float* cb1       = (const float*)d_in[16];
    const float* cb2       = (const float*)d_in[17];
    float* xout = (float*)d_out;

    float *p_xz, *p_proj, *p_dt, *p_fr, *p_b1, *p_b2;
    __nv_bfloat16 *p_lnh, *p_xmch, *p_yh, *p_r1h, *p_wie, *p_woe, *p_wde, *p_w1e, *p_w2e, *p_xpe;
    cudaGetSymbolAddress((void**)&p_xz,    g_xz);
    cudaGetSymbolAddress((void**)&p_proj,  g_proj);
    cudaGetSymbolAddress((void**)&p_dt,    g_dt);
    cudaGetSymbolAddress((void**)&p_fr,    g_fr);
    cudaGetSymbolAddress((void**)&p_b1,    g_b1);
    cudaGetSymbolAddress((void**)&p_b2,    g_b2);
    cudaGetSymbolAddress((void**)&p_lnh,   g_lnh);
    cudaGetSymbolAddress((void**)&p_xmch,  g_xmch);
    cudaGetSymbolAddress((void**)&p_yh,    g_yh);
    cudaGetSymbolAddress((void**)&p_r1h,   g_r1h);
    cudaGetSymbolAddress((void**)&p_wie,   g_wie);
    cudaGetSymbolAddress((void**)&p_woe,   g_woe);
    cudaGetSymbolAddress((void**)&p_wde,   g_wde);
    cudaGetSymbolAddress((void**)&p_w1e,   g_w1e);
    cudaGetSymbolAddress((void**)&p_w2e,   g_w2e);
    cudaGetSymbolAddress((void**)&p_xpe,   g_xpe);

    cudaFuncSetAttribute(k_fft1024r4, cudaFuncAttributeMaxDynamicSharedMemorySize, FFT_SMEM);

    cudaMemcpyAsync(xout, x_in, (size_t)ROWS*DIM*sizeof(float), cudaMemcpyDeviceToDevice, 0);

    k_build<<<(4*256*256 + 255)/256, 256>>>(cw1, cw2, cb1, cb2);
    k_wext_all<<<(WN_TOT + 255)/256, 256>>>(in_proj_w, out_proj_w, dt_proj_w, x_proj_w);

    for (int blk = 0; blk < 2; blk++){
        // ---- Mamba ----
        if (blk == 0)
            k_layernorm<<<ROWS, 256>>>(xout, ln_w, ln_b, p_lnh);
        k_hgemm<0,4,4,1,0,1><<<dim3(16,16,1), 256>>>(512,
            p_lnh, DIM, 0, p_wie, 512, 0, p_xz, 2*DI, 0, nullptr, 0);
        k_conv_silu<<<(ROWS*DI + 255)/256, 256>>>(conv_w, conv_b);
        k_hgemm<0,1,2,1,0,2><<<dim3(4,64,1), 256>>>(1024,
            p_xmch, DI, 0, p_xpe, 1024, 0, p_proj, 256, 0, nullptr, 0);
        k_hgemm<1,2,4,0,0,1><<<dim3(8,32,1), 256>>>(32,
            p_proj, 256, 0, p_wde, 32, 0, p_dt, DI, 0, dt_proj_b, 0);
        k_scan2<<<256, 256>>>(A_log, Dv);
        k_hgemm<2,2,2,1,0,2><<<dim3(8,32,1), 256>>>(1024,
            p_yh, DI, 0, p_woe, 1024, 0, xout, DIM, 0, nullptr, 0);

        // ---- EinFFT ----
        k_layernorm_fft<<<ROWS, 256>>>(xout, norm2_w, norm2_b);
        k_fft1024r4<<<256, 512, FFT_SMEM>>>(-1.f);
        k_hgemm<3,2,2,0,1,1><<<dim3(4,32,4), 256>>>(256,
            p_fr, 1024, 256, p_w1e, 256, 256*256, p_r1h, 1024, 256, p_b1, 256);
        k_hgemm<4,2,2,1,0,2><<<dim3(4,32,4), 256>>>(256,
            p_r1h, 1024, 256, p_w2e, 256, 256*256, p_fr, 1024, 256, p_b2, 256);
        k_fft1024r4<<<256, 512, FFT_SMEM>>>(1.f);
        k_fft4_inv_ln<<<ROWS, 128>>>(xout, blk == 0 ? 1 : 0, ln_w, ln_b);
    }
}